// round 13
// baseline (speedup 1.0000x reference)
#include <cuda_runtime.h>
#include <cuda_bf16.h>
#include <cstdint>
#include <math.h>

// ---------------------------------------------------------------------------
// Problem constants
// ---------------------------------------------------------------------------
static constexpr int kB = 8;
static constexpr int kS = 2048;
static constexpr int kD = 256;
static constexpr int kM = kB * kS;
static constexpr int QCH = 64;       // colsum: 32 rows per chunk
static constexpr int N_KCHUNK = 32;  // u-partial split over keys
static constexpr int NXT = kS / 256; // 8 n-tiles per batch row

// Scratch (static device memory)
// Blocked layout: block = [128 rows x 32 cols] = 16KB, SW128-swizzled.
__device__ float g_Nb[kM * kD];                        // tf32-rounded nodes, blocked
__device__ float g_Wh[2 * kD * kD];                    // weight hi, blocked (q,k)
__device__ float g_Wl[2 * kD * kD];                    // weight lo, blocked (q,k)
__device__ float g_Qb[kB * kS * kD];                   // tf32 q, blocked
__device__ float g_Kb[kB * kS * kD];                   // tf32 k, blocked
__device__ __nv_bfloat16 g_E[(size_t)kB * kS * kS];    // exp scores (bf16)
__device__ float g_rpart[NXT * kB * kS];
__device__ float g_wpart[QCH * kB * kS];
__device__ float g_upart[N_KCHUNK * kB * kD];          // u partials
__device__ float g_swpart[N_KCHUNK * kB];              // sum-of-w partials

#if defined(__CUDA_ARCH__) && defined(__CUDA_ARCH_FEAT_SM103_ALL)
#define HAS_TCGEN05 1
#else
#define HAS_TCGEN05 0
#endif

#define SMEM_SWIZZLE_128B(byte_offset) \
    ((byte_offset) ^ (((byte_offset) >> 3) & 0x70))

__device__ __forceinline__ uint32_t smem_to_u32_gen(const void* p) {
    uint32_t a;
    asm("{ .reg .u64 t; cvta.to.shared.u64 t, %1; cvt.u32.u64 %0, t; }"
        : "=r"(a) : "l"(p));
    return a;
}

__device__ __forceinline__ float to_tf32(float x) {
    float y;
    asm("cvt.rna.tf32.f32 %0, %1;" : "=f"(y) : "f"(x));
    return y;
}

__device__ __forceinline__ uint32_t pack_bf16x2(float lo, float hi) {
    uint32_t r;
    asm("cvt.rn.bf16x2.f32 %0, %1, %2;" : "=r"(r) : "f"(hi), "f"(lo));
    return r;
}

// float-index offset of element (r in [0,128), c in [0,32)) in blocked layout
__device__ __forceinline__ size_t qk_blk_off(int gmtile, int kchunk, int r, int c) {
    uint32_t byte = (uint32_t)(r * 128 + (c >> 2) * 16);
    uint32_t sw = SMEM_SWIZZLE_128B(byte) + (uint32_t)(c & 3) * 4;
    return ((size_t)(gmtile * 8 + kchunk) << 12) + (sw >> 2);
}

#if HAS_TCGEN05
__device__ __forceinline__ uint32_t elect_one_pred() {
    uint32_t pred;
    asm volatile(
        "{\n\t.reg .pred p;\n\t"
        "elect.sync _|p, 0xFFFFFFFF;\n\t"
        "selp.b32 %0, 1, 0, p;\n\t}"
        : "=r"(pred));
    return pred;
}

#define TCGEN05_ALLOC(smem_result_addr, nCols) \
    asm volatile("tcgen05.alloc.cta_group::1.sync.aligned.shared::cta.b32 [%0], %1;" \
                 :: "r"((uint32_t)(smem_result_addr)), "r"((uint32_t)(nCols)) : "memory")
#define TCGEN05_DEALLOC(tmem_addr, nCols) \
    asm volatile("tcgen05.dealloc.cta_group::1.sync.aligned.b32 %0, %1;" \
                 :: "r"(tmem_addr), "r"((uint32_t)(nCols)))
#define TCGEN05_RELINQUISH() \
    asm volatile("tcgen05.relinquish_alloc_permit.cta_group::1.sync.aligned;")
#define TCGEN05_COMMIT(mbar_smem_addr) \
    asm volatile("tcgen05.commit.cta_group::1.mbarrier::arrive::one.shared::cluster.b64 [%0];" \
                 :: "r"((uint32_t)(mbar_smem_addr)) : "memory")
#define TCGEN05_FENCE_AFTER() \
    asm volatile("tcgen05.fence::after_thread_sync;" ::: "memory")
#define TCGEN05_WAIT_LD() \
    asm volatile("tcgen05.wait::ld.sync.aligned;" ::: "memory")
#define MBARRIER_INIT(mbar_smem_addr, count) \
    asm volatile("mbarrier.init.shared.b64 [%0], %1;" \
                 :: "r"((uint32_t)(mbar_smem_addr)), "r"((uint32_t)(count)) : "memory")
#define MBARRIER_EXPECT_TX(mbar_smem_addr, tx_bytes) \
    asm volatile("mbarrier.arrive.expect_tx.shared.b64 _, [%0], %1;" \
                 :: "r"((uint32_t)(mbar_smem_addr)), "r"((uint32_t)(tx_bytes)) : "memory")

#define MBARRIER_WAIT_PARITY(mbar_smem_addr, phase_parity) do { \
    uint32_t _mbar = (uint32_t)(mbar_smem_addr); \
    uint32_t _parity = (uint32_t)(phase_parity); \
    uint32_t _done; \
    asm volatile( \
        "{\n\t.reg .pred p;\n\t" \
        "mbarrier.try_wait.parity.acquire.cta.shared::cta.b64 p, [%1], %2;\n\t" \
        "selp.b32 %0, 1, 0, p;\n\t}" \
        : "=r"(_done) : "r"(_mbar), "r"(_parity) : "memory"); \
    if (!_done) { \
        asm volatile( \
            "{\n\t.reg .pred P1;\n\t" \
            "WAIT_LOOP_%=:\n\t" \
            "mbarrier.try_wait.parity.acquire.cta.shared::cta.b64 P1, [%0], %1, 0x989680;\n\t" \
            "@P1 bra.uni WAIT_DONE_%=;\n\t" \
            "bra.uni WAIT_LOOP_%=;\n\t" \
            "WAIT_DONE_%=:\n\t}" \
            :: "r"(_mbar), "r"(_parity) : "memory"); \
    } \
} while(0)

#define TCGEN05_LD_32X32B_X32(r, tmem_addr) \
    asm volatile( \
        "tcgen05.ld.sync.aligned.32x32b.x32.b32 " \
        "{%0, %1, %2, %3, %4, %5, %6, %7, " \
        " %8, %9, %10, %11, %12, %13, %14, %15, " \
        " %16, %17, %18, %19, %20, %21, %22, %23, " \
        " %24, %25, %26, %27, %28, %29, %30, %31}, [%32];" \
        : "=r"((r)[0]),  "=r"((r)[1]),  "=r"((r)[2]),  "=r"((r)[3]), \
          "=r"((r)[4]),  "=r"((r)[5]),  "=r"((r)[6]),  "=r"((r)[7]), \
          "=r"((r)[8]),  "=r"((r)[9]),  "=r"((r)[10]), "=r"((r)[11]), \
          "=r"((r)[12]), "=r"((r)[13]), "=r"((r)[14]), "=r"((r)[15]), \
          "=r"((r)[16]), "=r"((r)[17]), "=r"((r)[18]), "=r"((r)[19]), \
          "=r"((r)[20]), "=r"((r)[21]), "=r"((r)[22]), "=r"((r)[23]), \
          "=r"((r)[24]), "=r"((r)[25]), "=r"((r)[26]), "=r"((r)[27]), \
          "=r"((r)[28]), "=r"((r)[29]), "=r"((r)[30]), "=r"((r)[31]) \
        : "r"(tmem_addr))

#define TCGEN05_MMA_TF32_SS(d_tmem, a_desc, b_desc, idesc, enable_d) do { \
    uint32_t _en = (enable_d) ? 1u : 0u; \
    uint32_t _zero = 0u; \
    asm volatile( \
        "{\n\t.reg .pred p;\n\t" \
        "setp.ne.u32 p, %5, 0;\n\t" \
        "tcgen05.mma.cta_group::1.kind::tf32 [%0], %1, %2, %3, {%4, %4, %4, %4}, p;\n\t" \
        "}" \
        :: "r"(d_tmem), "l"(a_desc), "l"(b_desc), "r"(idesc), "r"(_zero), "r"(_en) \
        : "memory"); \
} while(0)

static constexpr uint64_t SMEM_DESC_BASE_SW128 =
    (uint64_t(2)  << 61) | (uint64_t(1) << 46) | (uint64_t(64) << 32) | (uint64_t(1) << 16);
#define MAKE_SMEM_DESC(base_addr) \
    (SMEM_DESC_BASE_SW128 | ((uint64_t)((base_addr) >> 4) & 0x3FFF))

#define CP_ASYNC_BULK(dst_smem, src_gmem, bytes, mbar) \
    asm volatile("cp.async.bulk.shared::cta.global.mbarrier::complete_tx::bytes " \
                 "[%0], [%1], %2, [%3];" \
                 :: "r"((uint32_t)(dst_smem)), "l"(src_gmem), \
                    "r"((uint32_t)(bytes)), "r"((uint32_t)(mbar)) : "memory")

// IDESC: tf32, F32 accum
static constexpr uint32_t IDESC_128x256 =
    (1u << 4) | (2u << 7) | (2u << 10) | ((256 / 8) << 17) | ((128 / 16) << 24);
static constexpr uint32_t IDESC_128x128 =
    (1u << 4) | (2u << 7) | (2u << 10) | ((128 / 8) << 17) | ((128 / 16) << 24);
#endif  // HAS_TCGEN05

// ---------------------------------------------------------------------------
// Prep 1: nodes -> tf32-rounded, blocked-swizzled. grid (8, kM/128).
// ---------------------------------------------------------------------------
__global__ __launch_bounds__(256)
void nodes_prep(const float* __restrict__ src, float* __restrict__ Nb)
{
    const int kc = blockIdx.x;
    const int mt = blockIdx.y;
    const int tid = threadIdx.x;
    float* blk = Nb + (((size_t)mt * 8 + kc) << 12);
#pragma unroll
    for (int t = 0; t < 4; t++) {
        int idx = tid + t * 256;
        int row = idx >> 3, c4 = idx & 7;
        float4 v = *(const float4*)(src + (size_t)(mt * 128 + row) * kD + kc * 32 + c4 * 4);
        v.x = to_tf32(v.x); v.y = to_tf32(v.y);
        v.z = to_tf32(v.z); v.w = to_tf32(v.w);
        uint32_t sw = SMEM_SWIZZLE_128B((uint32_t)(row * 128 + c4 * 16));
        *(float4*)((char*)blk + sw) = v;
    }
}

// ---------------------------------------------------------------------------
// Prep 2: q,k weights -> (hi, lo) tf32 split, blocked. grid (8, 2, 2).
// ---------------------------------------------------------------------------
__global__ __launch_bounds__(256)
void wsplit_prep(const float* __restrict__ Wq, const float* __restrict__ Wk,
                 float* __restrict__ Wh, float* __restrict__ Wl)
{
    const int kc = blockIdx.x;
    const int mt = blockIdx.y;
    const int w  = blockIdx.z;
    const int tid = threadIdx.x;
    const float* W = (w == 0) ? Wq : Wk;
    float* bh = Wh + (size_t)w * (kD * kD) + (((size_t)mt * 8 + kc) << 12);
    float* bl = Wl + (size_t)w * (kD * kD) + (((size_t)mt * 8 + kc) << 12);
#pragma unroll
    for (int t = 0; t < 4; t++) {
        int idx = tid + t * 256;
        int row = idx >> 3, c4 = idx & 7;
        float4 v = *(const float4*)(W + (size_t)(mt * 128 + row) * kD + kc * 32 + c4 * 4);
        float4 h, l;
        h.x = to_tf32(v.x); l.x = to_tf32(v.x - h.x);
        h.y = to_tf32(v.y); l.y = to_tf32(v.y - h.y);
        h.z = to_tf32(v.z); l.z = to_tf32(v.z - h.z);
        h.w = to_tf32(v.w); l.w = to_tf32(v.w - h.w);
        uint32_t sw = SMEM_SWIZZLE_128B((uint32_t)(row * 128 + c4 * 16));
        *(float4*)((char*)bh + sw) = h;
        *(float4*)((char*)bl + sw) = l;
    }
}

// ---------------------------------------------------------------------------
// Pipelined projection GEMM (q,k only), BM=128, BN=128,
// grid (2 nx, 128 my, 2 w). C = tf32( A @ (Wh+Wl)^T + bias ) -> blocked.
// ---------------------------------------------------------------------------
static constexpr int PJ_STAGE = 49152;
static constexpr int PJ_SMEM = 2048 + 2 * PJ_STAGE;   // 100352

__global__ __launch_bounds__(256)
void proj_gemm(const float* __restrict__ Nb,
               const float* __restrict__ Wh, const float* __restrict__ Wl,
               const float* __restrict__ b0, const float* __restrict__ b1,
               float* __restrict__ C0, float* __restrict__ C1)
{
    extern __shared__ __align__(1024) char smem[];
    const int tid = threadIdx.x;
    const int nx = blockIdx.x;
    const int my = blockIdx.y;
    const int w  = blockIdx.z;
    const float* bias = (w == 0) ? b0 : b1;
    float* C = (w == 0) ? C0 : C1;
    const float* WhB = Wh + (size_t)w * (kD * kD);
    const float* WlB = Wl + (size_t)w * (kD * kD);
    const int bn = nx * 128;
    const int bm = my * 128;

#if HAS_TCGEN05
    const uint32_t sb = smem_to_u32_gen(smem);
    const uint32_t m_done = sb + 32;
    float* s_bias = (float*)(smem + 1024);
    const int wid = tid >> 5;

    if (wid == 0) { TCGEN05_ALLOC(sb + 40, 128); TCGEN05_RELINQUISH(); }
    if (tid == 0) {
        MBARRIER_INIT(sb + 0, 1);
        MBARRIER_INIT(sb + 8, 1);
        MBARRIER_INIT(sb + 16, 1);
        MBARRIER_INIT(sb + 24, 1);
        MBARRIER_INIT(m_done, 1);
    }
    if (tid < 128) s_bias[tid] = bias[bn + tid];
    __syncthreads();
    const uint32_t tmem = *(volatile uint32_t*)(smem + 40);

    uint64_t dA[2], dBh[2], dBl[2];
#pragma unroll
    for (int s = 0; s < 2; s++) {
        uint32_t base = sb + 2048 + s * PJ_STAGE;
        dA[s]  = MAKE_SMEM_DESC(base);
        dBh[s] = MAKE_SMEM_DESC(base + 16384);
        dBl[s] = MAKE_SMEM_DESC(base + 32768);
    }

    if (wid == 1) {
        if (elect_one_pred()) {
            for (int c = 0; c < 8; c++) {
                const int s = c & 1;
                const int i = c >> 1;
                const uint32_t m_full = sb + s * 8;
                const uint32_t m_emp  = sb + 16 + s * 8;
                const uint32_t st = sb + 2048 + s * PJ_STAGE;
                MBARRIER_WAIT_PARITY(m_emp, 1 ^ (i & 1));
                MBARRIER_EXPECT_TX(m_full, 49152u);
                CP_ASYNC_BULK(st,
                              Nb + (((size_t)my * 8 + c) << 12), 16384, m_full);
                CP_ASYNC_BULK(st + 16384,
                              WhB + (((size_t)nx * 8 + c) << 12), 16384, m_full);
                CP_ASYNC_BULK(st + 32768,
                              WlB + (((size_t)nx * 8 + c) << 12), 16384, m_full);
            }
        }
    } else if (wid == 0) {
        if (elect_one_pred()) {
            for (int c = 0; c < 8; c++) {
                const int s = c & 1;
                const int i = c >> 1;
                const uint32_t m_full = sb + s * 8;
                const uint32_t m_emp  = sb + 16 + s * 8;
                MBARRIER_WAIT_PARITY(m_full, i & 1);
#pragma unroll
                for (int k = 0; k < 4; k++)
                    TCGEN05_MMA_TF32_SS(tmem, dA[s] + k * 2, dBh[s] + k * 2,
                                        IDESC_128x128, (c > 0) || (k > 0));
#pragma unroll
                for (int k = 0; k < 4; k++)
                    TCGEN05_MMA_TF32_SS(tmem, dA[s] + k * 2, dBl[s] + k * 2,
                                        IDESC_128x128, true);
                TCGEN05_COMMIT(m_emp);
            }
            TCGEN05_COMMIT(m_done);
        }
    }

    MBARRIER_WAIT_PARITY(m_done, 0);
    TCGEN05_FENCE_AFTER();

    {
        const int lane = tid & 31;
        const int half = wid >> 2;
        const int mloc = (wid & 3) * 32 + lane;
        const int m = bm + mloc;
#pragma unroll
        for (int g = 0; g < 2; g++) {
            const int col0 = half * 64 + g * 32;
            uint32_t r[32];
            TCGEN05_LD_32X32B_X32(r, tmem + col0);
            TCGEN05_WAIT_LD();
#pragma unroll
            for (int j = 0; j < 32; j++)
                r[j] = __float_as_uint(
                    to_tf32(__uint_as_float(r[j]) + s_bias[col0 + j]));
            float* blk = C + (((size_t)(m >> 7) * 8 + nx * 4 + half * 2 + g) << 12);
#pragma unroll
            for (int j = 0; j < 8; j++) {
                uint32_t sw = SMEM_SWIZZLE_128B((uint32_t)(mloc * 128 + j * 16));
                *(float4*)((char*)blk + sw) = *(float4*)&r[j * 4];
            }
        }
    }
    __syncthreads();
    if (wid == 0) TCGEN05_DEALLOC(tmem, 128);

#else
    // SIMT fallback — reads blocked Nb / Wh / Wl.
    constexpr int BK = 16, TM = 8, TN = 8;
    float* As = (float*)smem;
    float* Bs = As + BK * 128;
    const int tx = tid & 15, ty = tid >> 4;

    float acc[TM][TN];
#pragma unroll
    for (int i = 0; i < TM; i++)
#pragma unroll
        for (int j = 0; j < TN; j++) acc[i][j] = 0.0f;

    for (int k0 = 0; k0 < kD; k0 += BK) {
        __syncthreads();
        for (int li = tid; li < 128 * BK; li += 256) {
            int row = li / BK, kc = li % BK;
            size_t off = qk_blk_off(nx, (k0 + kc) >> 5, row, (k0 + kc) & 31);
            As[kc * 128 + row] =
                Nb[qk_blk_off(my, (k0 + kc) >> 5, row, (k0 + kc) & 31)];
            Bs[kc * 128 + row] = WhB[off] + WlB[off];
        }
        __syncthreads();
#pragma unroll
        for (int kk = 0; kk < BK; kk++) {
            float a[TM], bb[TN];
            *(float4*)&a[0]  = *(const float4*)&As[kk * 128 + ty * TM];
            *(float4*)&a[4]  = *(const float4*)&As[kk * 128 + ty * TM + 4];
            *(float4*)&bb[0] = *(const float4*)&Bs[kk * 128 + tx * TN];
            *(float4*)&bb[4] = *(const float4*)&Bs[kk * 128 + tx * TN + 4];
#pragma unroll
            for (int i = 0; i < TM; i++)
#pragma unroll
                for (int j = 0; j < TN; j++)
                    acc[i][j] = fmaf(a[i], bb[j], acc[i][j]);
        }
    }
    const int row0 = bm + ty * TM, col0 = bn + tx * TN;
#pragma unroll
    for (int i = 0; i < TM; i++)
#pragma unroll
        for (int j = 0; j < TN; j++) {
            float v = acc[i][j] + bias[col0 + j];
            int m = row0 + i, n = col0 + j;
            C[qk_blk_off(m >> 7, n >> 5, m & 127, n & 31)] = to_tf32(v);
        }
#endif
}

// ---------------------------------------------------------------------------
// Scores GEMM (R11 config — no cluster): E = exp((q.k)/16)*maskfac bf16 +
// rowsum partials. BM=128, BN=256, 2-stage bulk pipeline, 2 CTAs/SM.
// grid (8 nx, 16 my, 8 bz).
// ---------------------------------------------------------------------------
static constexpr int SC_STAGE = 49152;
static constexpr int SC_SMEM = 2048 + 2 * SC_STAGE;   // 100352

__global__ __launch_bounds__(256)
void score_gemm(const float* __restrict__ Qb, const float* __restrict__ Kb,
                const int* __restrict__ mask, __nv_bfloat16* __restrict__ E,
                float* __restrict__ rpart, float scale)
{
    extern __shared__ __align__(1024) char smem[];
    const int tid = threadIdx.x;
    const int bz = blockIdx.z;
    __nv_bfloat16* C = E + (size_t)bz * kS * kS;
    const int* mk = mask + (size_t)bz * kS;

    const int my = blockIdx.y;          // m tile (128 rows)
    const int nx = blockIdx.x;          // n tile (256 cols)
    const int bm = my * 128;
    const int bn = nx * 256;

#if HAS_TCGEN05
    const uint32_t sb = smem_to_u32_gen(smem);
    const uint32_t m_done = sb + 32;
    float* s_rs2 = (float*)(smem + 256);
    float* s_mf  = (float*)(smem + 1024);
    const int wid = tid >> 5;

    if (wid == 0) { TCGEN05_ALLOC(sb + 40, 256); TCGEN05_RELINQUISH(); }
    if (tid == 0) {
        MBARRIER_INIT(sb + 0, 1);
        MBARRIER_INIT(sb + 8, 1);
        MBARRIER_INIT(sb + 16, 1);
        MBARRIER_INIT(sb + 24, 1);
        MBARRIER_INIT(m_done, 1);
    }
    s_mf[tid] = (mk[bn + tid] != 0) ? 1.0f : 0.0f;
    __syncthreads();
    const uint32_t tmem = *(volatile uint32_t*)(smem + 40);

    uint64_t dA[2], dB[2];
#pragma unroll
    for (int s = 0; s < 2; s++) {
        uint32_t base = sb + 2048 + s * SC_STAGE;
        dA[s] = MAKE_SMEM_DESC(base);
        dB[s] = MAKE_SMEM_DESC(base + 16384);
    }

    const int amt  = bz * 16 + my;
    const int bmt0 = bz * 16 + nx * 2;

    if (wid == 1) {
        if (elect_one_pred()) {
            for (int c = 0; c < 8; c++) {
                const int s = c & 1;
                const int i = c >> 1;
                const uint32_t m_full = sb + s * 8;
                const uint32_t m_emp  = sb + 16 + s * 8;
                const uint32_t st = sb + 2048 + s * SC_STAGE;
                MBARRIER_WAIT_PARITY(m_emp, 1 ^ (i & 1));
                MBARRIER_EXPECT_TX(m_full, SC_STAGE);
                CP_ASYNC_BULK(st,
                              Qb + (((size_t)amt * 8 + c) << 12), 16384, m_full);
                CP_ASYNC_BULK(st + 16384,
                              Kb + (((size_t)bmt0 * 8 + c) << 12), 16384, m_full);
                CP_ASYNC_BULK(st + 32768,
                              Kb + (((size_t)(bmt0 + 1) * 8 + c) << 12), 16384, m_full);
            }
        }
    } else if (wid == 0) {
        if (elect_one_pred()) {
            for (int c = 0; c < 8; c++) {
                const int s = c & 1;
                const int i = c >> 1;
                const uint32_t m_full = sb + s * 8;
                const uint32_t m_emp  = sb + 16 + s * 8;
                MBARRIER_WAIT_PARITY(m_full, i & 1);
#pragma unroll
                for (int k = 0; k < 4; k++)
                    TCGEN05_MMA_TF32_SS(tmem, dA[s] + k * 2, dB[s] + k * 2,
                                        IDESC_128x256, (c > 0) || (k > 0));
                TCGEN05_COMMIT(m_emp);
            }
            TCGEN05_COMMIT(m_done);
        }
    }

    MBARRIER_WAIT_PARITY(m_done, 0);
    TCGEN05_FENCE_AFTER();

    // Epilogue: warps 0-3 keys 0-127, warps 4-7 keys 128-255 (same q rows).
    {
        const int lane = tid & 31;
        const int half = wid >> 2;
        const int qrow = (wid & 3) * 32 + lane;
        const int m = bm + qrow;
        __nv_bfloat16* crow = C + (size_t)m * kS + bn + half * 128;
        float rs = 0.0f;
#pragma unroll
        for (int g = 0; g < 4; g++) {
            const int col0 = half * 128 + g * 32;
            uint32_t r[32];
            TCGEN05_LD_32X32B_X32(r, tmem + col0);
            TCGEN05_WAIT_LD();
            float e[32];
#pragma unroll
            for (int j = 0; j < 32; j++) {
                e[j] = __expf(__uint_as_float(r[j]) * scale) * s_mf[col0 + j];
                rs += e[j];
            }
            uint32_t pk[16];
#pragma unroll
            for (int j = 0; j < 16; j++)
                pk[j] = pack_bf16x2(e[j * 2], e[j * 2 + 1]);
#pragma unroll
            for (int j = 0; j < 4; j++)
                *(uint4*)&crow[g * 32 + j * 8] = *(uint4*)&pk[j * 4];
        }
        if (half == 1) s_rs2[qrow] = rs;
        __syncthreads();
        if (half == 0)
            rpart[((size_t)nx * kB + bz) * kS + m] = rs + s_rs2[qrow];
    }
    __syncthreads();
    if (wid == 0) TCGEN05_DEALLOC(tmem, 256);

#else
    // SIMT fallback — reads blocked Q/K layout, writes bf16 E + rpart.
    constexpr int BK = 16, TM = 8, TN = 8;
    float* As = (float*)smem;
    float* Bs = As + BK * 128;
    const int tx = tid & 15, ty = tid >> 4;
    const int amt  = bz * 16 + my;
    const int bmt0 = bz * 16 + nx * 2;

    float rs[TM];
#pragma unroll
    for (int i = 0; i < TM; i++) rs[i] = 0.0f;

    for (int nh = 0; nh < 2; nh++) {
        const int bmtl = bmt0 + nh;
        float acc[TM][TN];
#pragma unroll
        for (int i = 0; i < TM; i++)
#pragma unroll
            for (int j = 0; j < TN; j++) acc[i][j] = 0.0f;

        for (int k0 = 0; k0 < kD; k0 += BK) {
            __syncthreads();
            for (int li = tid; li < 128 * BK; li += 256) {
                int row = li / BK, kc = li % BK;
                As[kc * 128 + row] =
                    Qb[qk_blk_off(amt, (k0 + kc) >> 5, row, (k0 + kc) & 31)];
                Bs[kc * 128 + row] =
                    Kb[qk_blk_off(bmtl, (k0 + kc) >> 5, row, (k0 + kc) & 31)];
            }
            __syncthreads();
#pragma unroll
            for (int kk = 0; kk < BK; kk++) {
                float a[TM], bb[TN];
                *(float4*)&a[0]  = *(const float4*)&As[kk * 128 + ty * TM];
                *(float4*)&a[4]  = *(const float4*)&As[kk * 128 + ty * TM + 4];
                *(float4*)&bb[0] = *(const float4*)&Bs[kk * 128 + tx * TN];
                *(float4*)&bb[4] = *(const float4*)&Bs[kk * 128 + tx * TN + 4];
#pragma unroll
                for (int i = 0; i < TM; i++)
#pragma unroll
                    for (int j = 0; j < TN; j++)
                        acc[i][j] = fmaf(a[i], bb[j], acc[i][j]);
            }
        }
        const int row0 = bm + ty * TM;
        const int col0 = bn + nh * 128 + tx * TN;
#pragma unroll
        for (int i = 0; i < TM; i++)
#pragma unroll
            for (int j = 0; j < TN; j++) {
                float e = __expf(acc[i][j] * scale)
                          * ((mk[col0 + j] != 0) ? 1.0f : 0.0f);
                C[(size_t)(row0 + i) * kS + col0 + j] = __float2bfloat16(e);
                rs[i] += e;
            }
        __syncthreads();
    }
#pragma unroll
    for (int i = 0; i < TM; i++) {
        float v = rs[i];
#pragma unroll
        for (int o = 8; o; o >>= 1) v += __shfl_xor_sync(0xffffffffu, v, o);
        if (tx == 0)
            rpart[((size_t)nx * kB + bz) * kS + bm + ty * TM + i] = v;
    }
#endif
}

// ---------------------------------------------------------------------------
// Column-sum stream over bf16 E with inline invr (from rpart partials).
// ---------------------------------------------------------------------------
__global__ __launch_bounds__(256)
void colsum_stream_kernel(const __nv_bfloat16* __restrict__ E,
                          const float* __restrict__ rpart,
                          float* __restrict__ wpart)
{
    __shared__ float s_inv[32];
    const int ch = blockIdx.x;
    const int b  = blockIdx.y;
    const int tid = threadIdx.x;

    if (tid < 32) {
        const size_t q = (size_t)b * kS + (size_t)ch * 32 + tid;
        float s = 0.0f;
#pragma unroll
        for (int c = 0; c < NXT; c++) s += rpart[(size_t)c * (kB * kS) + q];
        s_inv[tid] = 1.0f / s;
    }
    __syncthreads();

    const __nv_bfloat16* base = E + ((size_t)b * kS + (size_t)ch * 32) * kS;
    float wacc[8];
#pragma unroll
    for (int i = 0; i < 8; i++) wacc[i] = 0.0f;

    for (int r = 0; r < 32; r++) {
        const float s = s_inv[r];
        const __nv_bfloat16* p = base + (size_t)r * kS + tid * 8;
        uint4 v = *(const uint4*)p;
        const uint32_t pk[4] = {v.x, v.y, v.z, v.w};
#pragma unroll
        for (int i = 0; i < 4; i++) {
            float2 f = __bfloat1622float2(*(const __nv_bfloat162*)&pk[i]);
            wacc[i * 2]     = fmaf(f.x, s, wacc[i * 2]);
            wacc[i * 2 + 1] = fmaf(f.y, s, wacc[i * 2 + 1]);
        }
    }

    float* o = wpart + (size_t)ch * (kB * kS) + (size_t)b * kS + tid * 8;
    *(float4*)&o[0] = make_float4(wacc[0], wacc[1], wacc[2], wacc[3]);
    *(float4*)&o[4] = make_float4(wacc[4], wacc[5], wacc[6], wacc[7]);
}

// ---------------------------------------------------------------------------
// u_part: w segment from wpart in-block, then u = sum_k w_k nodes[k,e]
// (uses RAW fp32 nodes). Also writes sum-of-w partial. grid (32 kchunk, 8 b).
// ---------------------------------------------------------------------------
__global__ __launch_bounds__(256)
void upart_kernel(const float* __restrict__ wpart,
                  const float* __restrict__ nodes,
                  float* __restrict__ upart, float* __restrict__ swpart)
{
    __shared__ float ws[64];
    const int chunk = blockIdx.x;
    const int b     = blockIdx.y;
    const int tid   = threadIdx.x;

    if (tid < 64) {
        const int key = chunk * 64 + tid;
        float s = 0.0f;
#pragma unroll 8
        for (int c = 0; c < QCH; c++)
            s += wpart[(size_t)c * (kB * kS) + (size_t)b * kS + key];
        ws[tid] = s;
    }
    __syncthreads();

    if (tid == 0) {
        float s = 0.0f;
#pragma unroll
        for (int k = 0; k < 64; k++) s += ws[k];
        swpart[chunk * kB + b] = s;
    }

    const float* nb = nodes + ((size_t)b * kS + (size_t)chunk * 64) * kD;
    float s = 0.0f;
#pragma unroll
    for (int k = 0; k < 64; k++) s = fmaf(ws[k], nb[(size_t)k * kD + tid], s);
    upart[(size_t)(chunk * kB + b) * kD + tid] = s;
}

// ---------------------------------------------------------------------------
// Final: out[b,d] = ( sum_e u[b,e]*Wv[d,e] + sw[b]*bv[d] ) / S. grid (8 b).
// ---------------------------------------------------------------------------
__global__ __launch_bounds__(256)
void out_final_kernel(const float* __restrict__ upart,
                      const float* __restrict__ swpart,
                      const float* __restrict__ Wv,
                      const float* __restrict__ bv,
                      float* __restrict__ out)
{
    __shared__ float u_s[kD];
    __shared__ float sw_s;
    const int b = blockIdx.x;
    const int tid = threadIdx.x;

    {
        float s = 0.0f;
#pragma unroll
        for (int c = 0; c < N_KCHUNK; c++)
            s += upart[(size_t)(c * kB + b) * kD + tid];
        u_s[tid] = s;
    }
    if (tid == 0) {
        float s = 0.0f;
#pragma unroll
        for (int c = 0; c < N_KCHUNK; c++) s += swpart[c * kB + b];
        sw_s = s;
    }
    __syncthreads();

    const float* wrow = Wv + (size_t)tid * kD;   // Wv[d=tid, :]
    float acc = 0.0f;
#pragma unroll 8
    for (int e = 0; e < kD; e++) acc = fmaf(u_s[e], wrow[e], acc);
    out[b * kD + tid] = (acc + sw_s * bv[tid]) * (1.0f / (float)kS);
}

// ---------------------------------------------------------------------------
// Launch
// ---------------------------------------------------------------------------
extern "C" void kernel_launch(void* const* d_in, const int* in_sizes, int n_in,
                              void* d_out, int out_size)
{
    const float* nodes = (const float*)d_in[0];
    const int*   mask  = (const int*)  d_in[1];
    const float* Wq    = (const float*)d_in[2];
    const float* bq    = (const float*)d_in[3];
    const float* Wk    = (const float*)d_in[4];
    const float* bk    = (const float*)d_in[5];
    const float* Wv    = (const float*)d_in[6];
    const float* bv    = (const float*)d_in[7];
    float* out = (float*)d_out;

    float *Nb, *Wh, *Wl, *Qb, *Kb, *rpart, *wpart, *upart, *swpart;
    __nv_bfloat16* E;
    cudaGetSymbolAddress((void**)&Nb,     g_Nb);
    cudaGetSymbolAddress((void**)&Wh,     g_Wh);
    cudaGetSymbolAddress((void**)&Wl,     g_Wl);
    cudaGetSymbolAddress((void**)&Qb,     g_Qb);
    cudaGetSymbolAddress((void**)&Kb,     g_Kb);
    cudaGetSymbolAddress((void**)&E,      g_E);
    cudaGetSymbolAddress((void**)&rpart,  g_rpart);
    cudaGetSymbolAddress((void**)&wpart,  g_wpart);
    cudaGetSymbolAddress((void**)&upart,  g_upart);
    cudaGetSymbolAddress((void**)&swpart, g_swpart);

    cudaFuncSetAttribute(proj_gemm,
                         cudaFuncAttributeMaxDynamicSharedMemorySize, PJ_SMEM);
    cudaFuncSetAttribute(score_gemm,
                         cudaFuncAttributeMaxDynamicSharedMemorySize, SC_SMEM);

    dim3 blk(256);

    // 0. Prep: nodes -> blocked tf32; q,k weights -> blocked hi/lo split.
    nodes_prep<<<dim3(8, kM / 128), blk>>>(nodes, Nb);
    wsplit_prep<<<dim3(8, 2, 2), blk>>>(Wq, Wk, Wh, Wl);

    // 1. Projections (q,k only): grid (2 nx, 128 my, 2 w), 2 CTAs/SM.
    dim3 gproj(2, kM / 128, 2);
    proj_gemm<<<gproj, blk, PJ_SMEM>>>(Nb, Wh, Wl, bq, bk, Qb, Kb);

    // 2. Scores -> E = exp(score/16) bf16 (masked = 0) + rowsum partials.
    dim3 gsc(kS / 256, kS / 128, kB);
    score_gemm<<<gsc, blk, SC_SMEM>>>(Qb, Kb, mask, E, rpart, 0.0625f);

    // 3. colsum (inline invr); u = w.nodes partials; final tiny contraction.
    colsum_stream_kernel<<<dim3(QCH, kB), blk>>>(E, rpart, wpart);
    upart_kernel<<<dim3(N_KCHUNK, kB), blk>>>(wpart, nodes, upart, swpart);
    out_final_kernel<<<kB, blk>>>(upart, swpart, Wv, bv, out);
}

// round 14
// speedup vs baseline: 1.3343x; 1.3343x over previous
#include <cuda_runtime.h>
#include <cuda_bf16.h>
#include <cuda_fp16.h>
#include <cstdint>
#include <math.h>

// ---------------------------------------------------------------------------
// Problem constants
// ---------------------------------------------------------------------------
static constexpr int kB = 8;
static constexpr int kS = 2048;
static constexpr int kD = 256;
static constexpr int kM = kB * kS;
static constexpr int QCH = 64;       // colsum: 32 rows per chunk
static constexpr int N_KCHUNK = 32;  // output split over keys
static constexpr int NXT = kS / 256; // 8 n-tiles per batch row

// Scratch (static device memory)
// fp32 blocked layout: block = [128 rows x 32 cols] = 16KB, SW128-swizzled.
// fp16 blocked layout: block = [128 rows x 64 cols] = 16KB, SW128-swizzled.
__device__ float  g_Nb[kM * kD];                       // tf32-rounded nodes, blocked
__device__ float  g_Wh[3 * kD * kD];                   // weight hi, blocked (q,k,v)
__device__ float  g_Wl[2 * kD * kD];                   // weight lo, blocked (q,k)
__device__ __half g_Qb[kB * kS * kD];                  // fp16 q, blocked
__device__ __half g_Kb[kB * kS * kD];                  // fp16 k, blocked
__device__ float  g_V[kB * kS * kD];                   // fp32 v, row-major
__device__ __nv_bfloat16 g_E[(size_t)kB * kS * kS];    // exp scores (bf16)
__device__ float g_rpart[NXT * kB * kS];
__device__ float g_wpart[QCH * kB * kS];
__device__ float g_opart[N_KCHUNK * kB * kD];

#if defined(__CUDA_ARCH__) && defined(__CUDA_ARCH_FEAT_SM103_ALL)
#define HAS_TCGEN05 1
#else
#define HAS_TCGEN05 0
#endif

#define SMEM_SWIZZLE_128B(byte_offset) \
    ((byte_offset) ^ (((byte_offset) >> 3) & 0x70))

__device__ __forceinline__ uint32_t smem_to_u32_gen(const void* p) {
    uint32_t a;
    asm("{ .reg .u64 t; cvta.to.shared.u64 t, %1; cvt.u32.u64 %0, t; }"
        : "=r"(a) : "l"(p));
    return a;
}

__device__ __forceinline__ float to_tf32(float x) {
    float y;
    asm("cvt.rna.tf32.f32 %0, %1;" : "=f"(y) : "f"(x));
    return y;
}

__device__ __forceinline__ uint32_t pack_bf16x2(float lo, float hi) {
    uint32_t r;
    asm("cvt.rn.bf16x2.f32 %0, %1, %2;" : "=r"(r) : "f"(hi), "f"(lo));
    return r;
}

__device__ __forceinline__ uint32_t pack_f16x2(float lo, float hi) {
    uint32_t r;
    asm("cvt.rn.f16x2.f32 %0, %1, %2;" : "=r"(r) : "f"(hi), "f"(lo));
    return r;
}

// fp32 blocked: byte offset helper (element index in floats)
__device__ __forceinline__ size_t qk_blk_off(int gmtile, int kchunk, int r, int c) {
    uint32_t byte = (uint32_t)(r * 128 + (c >> 2) * 16);
    uint32_t sw = SMEM_SWIZZLE_128B(byte) + (uint32_t)(c & 3) * 4;
    return ((size_t)(gmtile * 8 + kchunk) << 12) + (sw >> 2);
}

// fp16 blocked: BYTE offset of element (col in [0,256), row r in [0,128))
__device__ __forceinline__ size_t qk16_byte_off(int gmtile, int col, int r) {
    uint32_t base = (uint32_t)(r * 128 + ((col & 63) >> 3) * 16);
    uint32_t sw = SMEM_SWIZZLE_128B(base) + (uint32_t)(col & 7) * 2;
    return ((size_t)(gmtile * 4 + (col >> 6)) << 14) + sw;
}

#if HAS_TCGEN05
__device__ __forceinline__ uint32_t elect_one_pred() {
    uint32_t pred;
    asm volatile(
        "{\n\t.reg .pred p;\n\t"
        "elect.sync _|p, 0xFFFFFFFF;\n\t"
        "selp.b32 %0, 1, 0, p;\n\t}"
        : "=r"(pred));
    return pred;
}

#define TCGEN05_ALLOC(smem_result_addr, nCols) \
    asm volatile("tcgen05.alloc.cta_group::1.sync.aligned.shared::cta.b32 [%0], %1;" \
                 :: "r"((uint32_t)(smem_result_addr)), "r"((uint32_t)(nCols)) : "memory")
#define TCGEN05_DEALLOC(tmem_addr, nCols) \
    asm volatile("tcgen05.dealloc.cta_group::1.sync.aligned.b32 %0, %1;" \
                 :: "r"(tmem_addr), "r"((uint32_t)(nCols)))
#define TCGEN05_RELINQUISH() \
    asm volatile("tcgen05.relinquish_alloc_permit.cta_group::1.sync.aligned;")
#define TCGEN05_COMMIT(mbar_smem_addr) \
    asm volatile("tcgen05.commit.cta_group::1.mbarrier::arrive::one.shared::cluster.b64 [%0];" \
                 :: "r"((uint32_t)(mbar_smem_addr)) : "memory")
#define TCGEN05_FENCE_AFTER() \
    asm volatile("tcgen05.fence::after_thread_sync;" ::: "memory")
#define TCGEN05_WAIT_LD() \
    asm volatile("tcgen05.wait::ld.sync.aligned;" ::: "memory")
#define MBARRIER_INIT(mbar_smem_addr, count) \
    asm volatile("mbarrier.init.shared.b64 [%0], %1;" \
                 :: "r"((uint32_t)(mbar_smem_addr)), "r"((uint32_t)(count)) : "memory")
#define MBARRIER_EXPECT_TX(mbar_smem_addr, tx_bytes) \
    asm volatile("mbarrier.arrive.expect_tx.shared.b64 _, [%0], %1;" \
                 :: "r"((uint32_t)(mbar_smem_addr)), "r"((uint32_t)(tx_bytes)) : "memory")

#define MBARRIER_WAIT_PARITY(mbar_smem_addr, phase_parity) do { \
    uint32_t _mbar = (uint32_t)(mbar_smem_addr); \
    uint32_t _parity = (uint32_t)(phase_parity); \
    uint32_t _done; \
    asm volatile( \
        "{\n\t.reg .pred p;\n\t" \
        "mbarrier.try_wait.parity.acquire.cta.shared::cta.b64 p, [%1], %2;\n\t" \
        "selp.b32 %0, 1, 0, p;\n\t}" \
        : "=r"(_done) : "r"(_mbar), "r"(_parity) : "memory"); \
    if (!_done) { \
        asm volatile( \
            "{\n\t.reg .pred P1;\n\t" \
            "WAIT_LOOP_%=:\n\t" \
            "mbarrier.try_wait.parity.acquire.cta.shared::cta.b64 P1, [%0], %1, 0x989680;\n\t" \
            "@P1 bra.uni WAIT_DONE_%=;\n\t" \
            "bra.uni WAIT_LOOP_%=;\n\t" \
            "WAIT_DONE_%=:\n\t}" \
            :: "r"(_mbar), "r"(_parity) : "memory"); \
    } \
} while(0)

#define TCGEN05_LD_32X32B_X32(r, tmem_addr) \
    asm volatile( \
        "tcgen05.ld.sync.aligned.32x32b.x32.b32 " \
        "{%0, %1, %2, %3, %4, %5, %6, %7, " \
        " %8, %9, %10, %11, %12, %13, %14, %15, " \
        " %16, %17, %18, %19, %20, %21, %22, %23, " \
        " %24, %25, %26, %27, %28, %29, %30, %31}, [%32];" \
        : "=r"((r)[0]),  "=r"((r)[1]),  "=r"((r)[2]),  "=r"((r)[3]), \
          "=r"((r)[4]),  "=r"((r)[5]),  "=r"((r)[6]),  "=r"((r)[7]), \
          "=r"((r)[8]),  "=r"((r)[9]),  "=r"((r)[10]), "=r"((r)[11]), \
          "=r"((r)[12]), "=r"((r)[13]), "=r"((r)[14]), "=r"((r)[15]), \
          "=r"((r)[16]), "=r"((r)[17]), "=r"((r)[18]), "=r"((r)[19]), \
          "=r"((r)[20]), "=r"((r)[21]), "=r"((r)[22]), "=r"((r)[23]), \
          "=r"((r)[24]), "=r"((r)[25]), "=r"((r)[26]), "=r"((r)[27]), \
          "=r"((r)[28]), "=r"((r)[29]), "=r"((r)[30]), "=r"((r)[31]) \
        : "r"(tmem_addr))

#define TCGEN05_MMA_TF32_SS(d_tmem, a_desc, b_desc, idesc, enable_d) do { \
    uint32_t _en = (enable_d) ? 1u : 0u; \
    uint32_t _zero = 0u; \
    asm volatile( \
        "{\n\t.reg .pred p;\n\t" \
        "setp.ne.u32 p, %5, 0;\n\t" \
        "tcgen05.mma.cta_group::1.kind::tf32 [%0], %1, %2, %3, {%4, %4, %4, %4}, p;\n\t" \
        "}" \
        :: "r"(d_tmem), "l"(a_desc), "l"(b_desc), "r"(idesc), "r"(_zero), "r"(_en) \
        : "memory"); \
} while(0)

#define TCGEN05_MMA_F16_SS(d_tmem, a_desc, b_desc, idesc, enable_d) do { \
    uint32_t _en = (enable_d) ? 1u : 0u; \
    uint32_t _zero = 0u; \
    asm volatile( \
        "{\n\t.reg .pred p;\n\t" \
        "setp.ne.u32 p, %5, 0;\n\t" \
        "tcgen05.mma.cta_group::1.kind::f16 [%0], %1, %2, %3, {%4, %4, %4, %4}, p;\n\t" \
        "}" \
        :: "r"(d_tmem), "l"(a_desc), "l"(b_desc), "r"(idesc), "r"(_zero), "r"(_en) \
        : "memory"); \
} while(0)

static constexpr uint64_t SMEM_DESC_BASE_SW128 =
    (uint64_t(2)  << 61) | (uint64_t(1) << 46) | (uint64_t(64) << 32) | (uint64_t(1) << 16);
#define MAKE_SMEM_DESC(base_addr) \
    (SMEM_DESC_BASE_SW128 | ((uint64_t)((base_addr) >> 4) & 0x3FFF))

#define CP_ASYNC_BULK(dst_smem, src_gmem, bytes, mbar) \
    asm volatile("cp.async.bulk.shared::cta.global.mbarrier::complete_tx::bytes " \
                 "[%0], [%1], %2, [%3];" \
                 :: "r"((uint32_t)(dst_smem)), "l"(src_gmem), \
                    "r"((uint32_t)(bytes)), "r"((uint32_t)(mbar)) : "memory")

// IDESCs (F32 accum)
static constexpr uint32_t IDESC_TF32_128x128 =
    (1u << 4) | (2u << 7) | (2u << 10) | ((128 / 8) << 17) | ((128 / 16) << 24);
static constexpr uint32_t IDESC_F16_128x256 =
    (1u << 4) | (0u << 7) | (0u << 10) | ((256 / 8) << 17) | ((128 / 16) << 24);
#endif  // HAS_TCGEN05

// ---------------------------------------------------------------------------
// Prep 1: nodes -> tf32-rounded, blocked-swizzled. grid (8, kM/128).
// ---------------------------------------------------------------------------
__global__ __launch_bounds__(256)
void nodes_prep(const float* __restrict__ src, float* __restrict__ Nb)
{
    const int kc = blockIdx.x;
    const int mt = blockIdx.y;
    const int tid = threadIdx.x;
    float* blk = Nb + (((size_t)mt * 8 + kc) << 12);
#pragma unroll
    for (int t = 0; t < 4; t++) {
        int idx = tid + t * 256;
        int row = idx >> 3, c4 = idx & 7;
        float4 v = *(const float4*)(src + (size_t)(mt * 128 + row) * kD + kc * 32 + c4 * 4);
        v.x = to_tf32(v.x); v.y = to_tf32(v.y);
        v.z = to_tf32(v.z); v.w = to_tf32(v.w);
        uint32_t sw = SMEM_SWIZZLE_128B((uint32_t)(row * 128 + c4 * 16));
        *(float4*)((char*)blk + sw) = v;
    }
}

// ---------------------------------------------------------------------------
// Prep 2: weights -> (hi, lo) tf32 split, blocked. grid (8, 2, 3).
// Wh holds q,k,v hi; Wl holds q,k lo.
// ---------------------------------------------------------------------------
__global__ __launch_bounds__(256)
void wsplit_prep(const float* __restrict__ Wq, const float* __restrict__ Wk,
                 const float* __restrict__ Wv,
                 float* __restrict__ Wh, float* __restrict__ Wl)
{
    const int kc = blockIdx.x;
    const int mt = blockIdx.y;
    const int w  = blockIdx.z;
    const int tid = threadIdx.x;
    const float* W = (w == 0) ? Wq : (w == 1) ? Wk : Wv;
    float* bh = Wh + (size_t)w * (kD * kD) + (((size_t)mt * 8 + kc) << 12);
    float* bl = (w < 2) ? Wl + (size_t)w * (kD * kD) + (((size_t)mt * 8 + kc) << 12)
                        : nullptr;
#pragma unroll
    for (int t = 0; t < 4; t++) {
        int idx = tid + t * 256;
        int row = idx >> 3, c4 = idx & 7;
        float4 v = *(const float4*)(W + (size_t)(mt * 128 + row) * kD + kc * 32 + c4 * 4);
        float4 h, l;
        h.x = to_tf32(v.x); l.x = to_tf32(v.x - h.x);
        h.y = to_tf32(v.y); l.y = to_tf32(v.y - h.y);
        h.z = to_tf32(v.z); l.z = to_tf32(v.z - h.z);
        h.w = to_tf32(v.w); l.w = to_tf32(v.w - h.w);
        uint32_t sw = SMEM_SWIZZLE_128B((uint32_t)(row * 128 + c4 * 16));
        *(float4*)((char*)bh + sw) = h;
        if (bl) *(float4*)((char*)bl + sw) = l;
    }
}

// ---------------------------------------------------------------------------
// Pipelined projection GEMM, BM=128, BN=128, grid (2 nx, 128 my, 3 w).
//   q/k (w<2): C = fp16( A @ (Wh+Wl)^T + bias ) -> fp16 blocked
//   v  (w=2): C = A @ Wh^T + bias               -> row-major fp32
// ---------------------------------------------------------------------------
static constexpr int PJ_STAGE = 49152;
static constexpr int PJ_SMEM = 2048 + 2 * PJ_STAGE;   // 100352

__global__ __launch_bounds__(256)
void proj_gemm(const float* __restrict__ Nb,
               const float* __restrict__ Wh, const float* __restrict__ Wl,
               const float* __restrict__ b0, const float* __restrict__ b1,
               const float* __restrict__ b2,
               __half* __restrict__ C0, __half* __restrict__ C1,
               float* __restrict__ C2)
{
    extern __shared__ __align__(1024) char smem[];
    const int tid = threadIdx.x;
    const int nx = blockIdx.x;
    const int my = blockIdx.y;
    const int w  = blockIdx.z;
    const float* bias = (w == 0) ? b0 : (w == 1) ? b1 : b2;
    const bool two_pass = (w < 2);
    __half* Ch = (w == 0) ? C0 : C1;
    const float* WhB = Wh + (size_t)w * (kD * kD);
    const float* WlB = Wl + (size_t)w * (kD * kD);
    const int bn = nx * 128;
    const int bm = my * 128;

#if HAS_TCGEN05
    const uint32_t sb = smem_to_u32_gen(smem);
    const uint32_t m_done = sb + 32;
    float* s_bias = (float*)(smem + 1024);
    const int wid = tid >> 5;

    if (wid == 0) { TCGEN05_ALLOC(sb + 40, 128); TCGEN05_RELINQUISH(); }
    if (tid == 0) {
        MBARRIER_INIT(sb + 0, 1);
        MBARRIER_INIT(sb + 8, 1);
        MBARRIER_INIT(sb + 16, 1);
        MBARRIER_INIT(sb + 24, 1);
        MBARRIER_INIT(m_done, 1);
    }
    if (tid < 128) s_bias[tid] = bias[bn + tid];
    __syncthreads();
    const uint32_t tmem = *(volatile uint32_t*)(smem + 40);

    uint64_t dA[2], dBh[2], dBl[2];
#pragma unroll
    for (int s = 0; s < 2; s++) {
        uint32_t base = sb + 2048 + s * PJ_STAGE;
        dA[s]  = MAKE_SMEM_DESC(base);
        dBh[s] = MAKE_SMEM_DESC(base + 16384);
        dBl[s] = MAKE_SMEM_DESC(base + 32768);
    }

    const uint32_t tx_bytes = two_pass ? 49152u : 32768u;

    if (wid == 1) {
        if (elect_one_pred()) {
            for (int c = 0; c < 8; c++) {
                const int s = c & 1;
                const int i = c >> 1;
                const uint32_t m_full = sb + s * 8;
                const uint32_t m_emp  = sb + 16 + s * 8;
                const uint32_t st = sb + 2048 + s * PJ_STAGE;
                MBARRIER_WAIT_PARITY(m_emp, 1 ^ (i & 1));
                MBARRIER_EXPECT_TX(m_full, tx_bytes);
                CP_ASYNC_BULK(st,
                              Nb + (((size_t)my * 8 + c) << 12), 16384, m_full);
                CP_ASYNC_BULK(st + 16384,
                              WhB + (((size_t)nx * 8 + c) << 12), 16384, m_full);
                if (two_pass)
                    CP_ASYNC_BULK(st + 32768,
                                  WlB + (((size_t)nx * 8 + c) << 12), 16384, m_full);
            }
        }
    } else if (wid == 0) {
        if (elect_one_pred()) {
            for (int c = 0; c < 8; c++) {
                const int s = c & 1;
                const int i = c >> 1;
                const uint32_t m_full = sb + s * 8;
                const uint32_t m_emp  = sb + 16 + s * 8;
                MBARRIER_WAIT_PARITY(m_full, i & 1);
#pragma unroll
                for (int k = 0; k < 4; k++)
                    TCGEN05_MMA_TF32_SS(tmem, dA[s] + k * 2, dBh[s] + k * 2,
                                        IDESC_TF32_128x128, (c > 0) || (k > 0));
                if (two_pass) {
#pragma unroll
                    for (int k = 0; k < 4; k++)
                        TCGEN05_MMA_TF32_SS(tmem, dA[s] + k * 2, dBl[s] + k * 2,
                                            IDESC_TF32_128x128, true);
                }
                TCGEN05_COMMIT(m_emp);
            }
            TCGEN05_COMMIT(m_done);
        }
    }

    MBARRIER_WAIT_PARITY(m_done, 0);
    TCGEN05_FENCE_AFTER();

    // Epilogue: warps 0-3 cols 0-63, warps 4-7 cols 64-127.
    {
        const int lane = tid & 31;
        const int half = wid >> 2;
        const int mloc = (wid & 3) * 32 + lane;
        const int m = bm + mloc;
#pragma unroll
        for (int g = 0; g < 2; g++) {
            const int col0 = half * 64 + g * 32;
            uint32_t r[32];
            TCGEN05_LD_32X32B_X32(r, tmem + col0);
            TCGEN05_WAIT_LD();
            if (two_pass) {
                // fp16 output, blocked: block = gmtile*4 + nx*2 + half
                float e[32];
#pragma unroll
                for (int j = 0; j < 32; j++)
                    e[j] = __uint_as_float(r[j]) + s_bias[col0 + j];
                uint32_t pk[16];
#pragma unroll
                for (int j = 0; j < 16; j++)
                    pk[j] = pack_f16x2(e[j * 2], e[j * 2 + 1]);
                __half* blk = Ch + (((size_t)(m >> 7) * 4 + nx * 2 + half) << 13);
#pragma unroll
                for (int j = 0; j < 4; j++) {
                    uint32_t sw = SMEM_SWIZZLE_128B(
                        (uint32_t)(mloc * 128 + g * 64 + j * 16));
                    *(uint4*)((char*)blk + sw) = *(uint4*)&pk[j * 4];
                }
            } else {
#pragma unroll
                for (int j = 0; j < 32; j++)
                    r[j] = __float_as_uint(__uint_as_float(r[j]) + s_bias[col0 + j]);
                float* crow = C2 + (size_t)m * kD + bn + col0;
#pragma unroll
                for (int j = 0; j < 8; j++)
                    *(float4*)&crow[j * 4] = *(float4*)&r[j * 4];
            }
        }
    }
    __syncthreads();
    if (wid == 0) TCGEN05_DEALLOC(tmem, 128);

#else
    // SIMT fallback — reads blocked Nb / Wh / Wl.
    constexpr int BK = 16, TM = 8, TN = 8;
    float* As = (float*)smem;
    float* Bs = As + BK * 128;
    const int tx = tid & 15, ty = tid >> 4;

    float acc[TM][TN];
#pragma unroll
    for (int i = 0; i < TM; i++)
#pragma unroll
        for (int j = 0; j < TN; j++) acc[i][j] = 0.0f;

    for (int k0 = 0; k0 < kD; k0 += BK) {
        __syncthreads();
        for (int li = tid; li < 128 * BK; li += 256) {
            int row = li / BK, kc = li % BK;
            size_t off = qk_blk_off(nx, (k0 + kc) >> 5, row, (k0 + kc) & 31);
            As[kc * 128 + row] =
                Nb[qk_blk_off(my, (k0 + kc) >> 5, row, (k0 + kc) & 31)];
            float bw = WhB[off];
            if (two_pass) bw += WlB[off];
            Bs[kc * 128 + row] = bw;
        }
        __syncthreads();
#pragma unroll
        for (int kk = 0; kk < BK; kk++) {
            float a[TM], bb[TN];
            *(float4*)&a[0]  = *(const float4*)&As[kk * 128 + ty * TM];
            *(float4*)&a[4]  = *(const float4*)&As[kk * 128 + ty * TM + 4];
            *(float4*)&bb[0] = *(const float4*)&Bs[kk * 128 + tx * TN];
            *(float4*)&bb[4] = *(const float4*)&Bs[kk * 128 + tx * TN + 4];
#pragma unroll
            for (int i = 0; i < TM; i++)
#pragma unroll
                for (int j = 0; j < TN; j++)
                    acc[i][j] = fmaf(a[i], bb[j], acc[i][j]);
        }
    }
    const int row0 = bm + ty * TM, col0 = bn + tx * TN;
#pragma unroll
    for (int i = 0; i < TM; i++)
#pragma unroll
        for (int j = 0; j < TN; j++) {
            float v = acc[i][j] + bias[col0 + j];
            int m = row0 + i, n = col0 + j;
            if (two_pass)
                *(__half*)((char*)Ch + qk16_byte_off(m >> 7, n, m & 127)) =
                    __float2half_rn(v);
            else
                C2[(size_t)m * kD + n] = v;
        }
#endif
}

// ---------------------------------------------------------------------------
// Scores GEMM (fp16 inputs): E = exp((q.k)/16)*maskfac bf16 + rowsum partials.
// BM=128, BN=256. 4 K-chunks of 64 fp16, stages {Q 16K | K 32K} x2.
// grid (8 nx, 16 my, 8 bz), 2 CTAs/SM.
// ---------------------------------------------------------------------------
static constexpr int SC_STAGE = 49152;
static constexpr int SC_SMEM = 2048 + 2 * SC_STAGE;   // 100352

__global__ __launch_bounds__(256)
void score_gemm(const __half* __restrict__ Qb, const __half* __restrict__ Kb,
                const int* __restrict__ mask, __nv_bfloat16* __restrict__ E,
                float* __restrict__ rpart, float scale)
{
    extern __shared__ __align__(1024) char smem[];
    const int tid = threadIdx.x;
    const int bz = blockIdx.z;
    __nv_bfloat16* C = E + (size_t)bz * kS * kS;
    const int* mk = mask + (size_t)bz * kS;

    const int my = blockIdx.y;          // m tile (128 rows)
    const int nx = blockIdx.x;          // n tile (256 cols)
    const int bm = my * 128;
    const int bn = nx * 256;

#if HAS_TCGEN05
    const uint32_t sb = smem_to_u32_gen(smem);
    const uint32_t m_done = sb + 32;
    float* s_rs2 = (float*)(smem + 256);
    float* s_mf  = (float*)(smem + 1024);
    const int wid = tid >> 5;

    if (wid == 0) { TCGEN05_ALLOC(sb + 40, 256); TCGEN05_RELINQUISH(); }
    if (tid == 0) {
        MBARRIER_INIT(sb + 0, 1);
        MBARRIER_INIT(sb + 8, 1);
        MBARRIER_INIT(sb + 16, 1);
        MBARRIER_INIT(sb + 24, 1);
        MBARRIER_INIT(m_done, 1);
    }
    s_mf[tid] = (mk[bn + tid] != 0) ? 1.0f : 0.0f;
    __syncthreads();
    const uint32_t tmem = *(volatile uint32_t*)(smem + 40);

    uint64_t dA[2], dB[2];
#pragma unroll
    for (int s = 0; s < 2; s++) {
        uint32_t base = sb + 2048 + s * SC_STAGE;
        dA[s] = MAKE_SMEM_DESC(base);
        dB[s] = MAKE_SMEM_DESC(base + 16384);
    }

    const int amt  = bz * 16 + my;
    const int bmt0 = bz * 16 + nx * 2;

    if (wid == 1) {
        if (elect_one_pred()) {
            for (int c = 0; c < 4; c++) {      // 4 chunks of K=64 fp16
                const int s = c & 1;
                const int i = c >> 1;
                const uint32_t m_full = sb + s * 8;
                const uint32_t m_emp  = sb + 16 + s * 8;
                const uint32_t st = sb + 2048 + s * SC_STAGE;
                MBARRIER_WAIT_PARITY(m_emp, 1 ^ (i & 1));
                MBARRIER_EXPECT_TX(m_full, SC_STAGE);
                CP_ASYNC_BULK(st,
                              (const char*)Qb + (((size_t)amt * 4 + c) << 14),
                              16384, m_full);
                CP_ASYNC_BULK(st + 16384,
                              (const char*)Kb + (((size_t)bmt0 * 4 + c) << 14),
                              16384, m_full);
                CP_ASYNC_BULK(st + 32768,
                              (const char*)Kb + (((size_t)(bmt0 + 1) * 4 + c) << 14),
                              16384, m_full);
            }
        }
    } else if (wid == 0) {
        if (elect_one_pred()) {
            for (int c = 0; c < 4; c++) {
                const int s = c & 1;
                const int i = c >> 1;
                const uint32_t m_full = sb + s * 8;
                const uint32_t m_emp  = sb + 16 + s * 8;
                MBARRIER_WAIT_PARITY(m_full, i & 1);
#pragma unroll
                for (int k = 0; k < 4; k++)     // 4 x K=16 steps, +32B each
                    TCGEN05_MMA_F16_SS(tmem, dA[s] + k * 2, dB[s] + k * 2,
                                       IDESC_F16_128x256, (c > 0) || (k > 0));
                TCGEN05_COMMIT(m_emp);
            }
            TCGEN05_COMMIT(m_done);
        }
    }

    MBARRIER_WAIT_PARITY(m_done, 0);
    TCGEN05_FENCE_AFTER();

    // Epilogue: warps 0-3 keys 0-127, warps 4-7 keys 128-255 (same q rows).
    {
        const int lane = tid & 31;
        const int half = wid >> 2;
        const int qrow = (wid & 3) * 32 + lane;
        const int m = bm + qrow;
        __nv_bfloat16* crow = C + (size_t)m * kS + bn + half * 128;
        float rs = 0.0f;
#pragma unroll
        for (int g = 0; g < 4; g++) {
            const int col0 = half * 128 + g * 32;
            uint32_t r[32];
            TCGEN05_LD_32X32B_X32(r, tmem + col0);
            TCGEN05_WAIT_LD();
            float e[32];
#pragma unroll
            for (int j = 0; j < 32; j++) {
                e[j] = __expf(__uint_as_float(r[j]) * scale) * s_mf[col0 + j];
                rs += e[j];
            }
            uint32_t pk[16];
#pragma unroll
            for (int j = 0; j < 16; j++)
                pk[j] = pack_bf16x2(e[j * 2], e[j * 2 + 1]);
#pragma unroll
            for (int j = 0; j < 4; j++)
                *(uint4*)&crow[g * 32 + j * 8] = *(uint4*)&pk[j * 4];
        }
        if (half == 1) s_rs2[qrow] = rs;
        __syncthreads();
        if (half == 0)
            rpart[((size_t)nx * kB + bz) * kS + m] = rs + s_rs2[qrow];
    }
    __syncthreads();
    if (wid == 0) TCGEN05_DEALLOC(tmem, 256);

#else
    // SIMT fallback — reads fp16 blocked Q/K, writes bf16 E + rpart.
    constexpr int BK = 16, TM = 8, TN = 8;
    float* As = (float*)smem;
    float* Bs = As + BK * 128;
    const int tx = tid & 15, ty = tid >> 4;
    const int amt  = bz * 16 + my;
    const int bmt0 = bz * 16 + nx * 2;

    float rs[TM];
#pragma unroll
    for (int i = 0; i < TM; i++) rs[i] = 0.0f;

    for (int nh = 0; nh < 2; nh++) {
        const int bmtl = bmt0 + nh;
        float acc[TM][TN];
#pragma unroll
        for (int i = 0; i < TM; i++)
#pragma unroll
            for (int j = 0; j < TN; j++) acc[i][j] = 0.0f;

        for (int k0 = 0; k0 < kD; k0 += BK) {
            __syncthreads();
            for (int li = tid; li < 128 * BK; li += 256) {
                int row = li / BK, kc = li % BK;
                As[kc * 128 + row] = __half2float(*(const __half*)
                    ((const char*)Qb + qk16_byte_off(amt, k0 + kc, row)));
                Bs[kc * 128 + row] = __half2float(*(const __half*)
                    ((const char*)Kb + qk16_byte_off(bmtl, k0 + kc, row)));
            }
            __syncthreads();
#pragma unroll
            for (int kk = 0; kk < BK; kk++) {
                float a[TM], bb[TN];
                *(float4*)&a[0]  = *(const float4*)&As[kk * 128 + ty * TM];
                *(float4*)&a[4]  = *(const float4*)&As[kk * 128 + ty * TM + 4];
                *(float4*)&bb[0] = *(const float4*)&Bs[kk * 128 + tx * TN];
                *(float4*)&bb[4] = *(const float4*)&Bs[kk * 128 + tx * TN + 4];
#pragma unroll
                for (int i = 0; i < TM; i++)
#pragma unroll
                    for (int j = 0; j < TN; j++)
                        acc[i][j] = fmaf(a[i], bb[j], acc[i][j]);
            }
        }
        const int row0 = bm + ty * TM;
        const int col0 = bn + nh * 128 + tx * TN;
#pragma unroll
        for (int i = 0; i < TM; i++)
#pragma unroll
            for (int j = 0; j < TN; j++) {
                float e = __expf(acc[i][j] * scale)
                          * ((mk[col0 + j] != 0) ? 1.0f : 0.0f);
                C[(size_t)(row0 + i) * kS + col0 + j] = __float2bfloat16(e);
                rs[i] += e;
            }
        __syncthreads();
    }
#pragma unroll
    for (int i = 0; i < TM; i++) {
        float v = rs[i];
#pragma unroll
        for (int o = 8; o; o >>= 1) v += __shfl_xor_sync(0xffffffffu, v, o);
        if (tx == 0)
            rpart[((size_t)nx * kB + bz) * kS + bm + ty * TM + i] = v;
    }
#endif
}

// ---------------------------------------------------------------------------
// Column-sum stream over bf16 E with inline invr (from rpart partials).
// ---------------------------------------------------------------------------
__global__ __launch_bounds__(256)
void colsum_stream_kernel(const __nv_bfloat16* __restrict__ E,
                          const float* __restrict__ rpart,
                          float* __restrict__ wpart)
{
    __shared__ float s_inv[32];
    const int ch = blockIdx.x;
    const int b  = blockIdx.y;
    const int tid = threadIdx.x;

    if (tid < 32) {
        const size_t q = (size_t)b * kS + (size_t)ch * 32 + tid;
        float s = 0.0f;
#pragma unroll
        for (int c = 0; c < NXT; c++) s += rpart[(size_t)c * (kB * kS) + q];
        s_inv[tid] = 1.0f / s;
    }
    __syncthreads();

    const __nv_bfloat16* base = E + ((size_t)b * kS + (size_t)ch * 32) * kS;
    float wacc[8];
#pragma unroll
    for (int i = 0; i < 8; i++) wacc[i] = 0.0f;

    for (int r = 0; r < 32; r++) {
        const float s = s_inv[r];
        const __nv_bfloat16* p = base + (size_t)r * kS + tid * 8;
        uint4 v = *(const uint4*)p;
        const uint32_t pk[4] = {v.x, v.y, v.z, v.w};
#pragma unroll
        for (int i = 0; i < 4; i++) {
            float2 f = __bfloat1622float2(*(const __nv_bfloat162*)&pk[i]);
            wacc[i * 2]     = fmaf(f.x, s, wacc[i * 2]);
            wacc[i * 2 + 1] = fmaf(f.y, s, wacc[i * 2 + 1]);
        }
    }

    float* o = wpart + (size_t)ch * (kB * kS) + (size_t)b * kS + tid * 8;
    *(float4*)&o[0] = make_float4(wacc[0], wacc[1], wacc[2], wacc[3]);
    *(float4*)&o[4] = make_float4(wacc[4], wacc[5], wacc[6], wacc[7]);
}

// ---------------------------------------------------------------------------
// out_part: w segment reduced from wpart in-block, then o = sum_k w_k V[k,d].
// ---------------------------------------------------------------------------
__global__ __launch_bounds__(256)
void out_part_kernel(const float* __restrict__ wpart, const float* __restrict__ V,
                     float* __restrict__ opart)
{
    __shared__ float ws[64];
    const int chunk = blockIdx.x;
    const int b     = blockIdx.y;
    const int tid   = threadIdx.x;

    if (tid < 64) {
        const int key = chunk * 64 + tid;
        float s = 0.0f;
#pragma unroll 8
        for (int c = 0; c < QCH; c++)
            s += wpart[(size_t)c * (kB * kS) + (size_t)b * kS + key];
        ws[tid] = s;
    }
    __syncthreads();

    const float* vb = V + ((size_t)b * kS + (size_t)chunk * 64) * kD;
    float s = 0.0f;
#pragma unroll
    for (int k = 0; k < 64; k++) s = fmaf(ws[k], vb[(size_t)k * kD + tid], s);
    opart[(size_t)(chunk * kB + b) * kD + tid] = s;
}

__global__ __launch_bounds__(256)
void out_reduce_kernel(const float* __restrict__ opart, float* __restrict__ out)
{
    const int i = blockIdx.x * 256 + threadIdx.x;
    float s = 0.0f;
#pragma unroll
    for (int c = 0; c < N_KCHUNK; c++) s += opart[(size_t)c * (kB * kD) + i];
    out[i] = s * (1.0f / (float)kS);
}

// ---------------------------------------------------------------------------
// Launch
// ---------------------------------------------------------------------------
extern "C" void kernel_launch(void* const* d_in, const int* in_sizes, int n_in,
                              void* d_out, int out_size)
{
    const float* nodes = (const float*)d_in[0];
    const int*   mask  = (const int*)  d_in[1];
    const float* Wq    = (const float*)d_in[2];
    const float* bq    = (const float*)d_in[3];
    const float* Wk    = (const float*)d_in[4];
    const float* bk    = (const float*)d_in[5];
    const float* Wv    = (const float*)d_in[6];
    const float* bv    = (const float*)d_in[7];
    float* out = (float*)d_out;

    float *Nb, *Wh, *Wl, *V, *rpart, *wpart, *opart;
    __half *Qb, *Kb;
    __nv_bfloat16* E;
    cudaGetSymbolAddress((void**)&Nb,    g_Nb);
    cudaGetSymbolAddress((void**)&Wh,    g_Wh);
    cudaGetSymbolAddress((void**)&Wl,    g_Wl);
    cudaGetSymbolAddress((void**)&Qb,    g_Qb);
    cudaGetSymbolAddress((void**)&Kb,    g_Kb);
    cudaGetSymbolAddress((void**)&V,     g_V);
    cudaGetSymbolAddress((void**)&E,     g_E);
    cudaGetSymbolAddress((void**)&rpart, g_rpart);
    cudaGetSymbolAddress((void**)&wpart, g_wpart);
    cudaGetSymbolAddress((void**)&opart, g_opart);

    cudaFuncSetAttribute(proj_gemm,
                         cudaFuncAttributeMaxDynamicSharedMemorySize, PJ_SMEM);
    cudaFuncSetAttribute(score_gemm,
                         cudaFuncAttributeMaxDynamicSharedMemorySize, SC_SMEM);

    dim3 blk(256);

    // 0. Prep: nodes -> blocked tf32; weights -> blocked hi/lo split.
    nodes_prep<<<dim3(8, kM / 128), blk>>>(nodes, Nb);
    wsplit_prep<<<dim3(8, 2, 3), blk>>>(Wq, Wk, Wv, Wh, Wl);

    // 1. Projections: grid (2 nx, 128 my, 3 w), 2 CTAs/SM.
    //    q,k -> fp16 blocked; v -> fp32 row-major.
    dim3 gproj(2, kM / 128, 3);
    proj_gemm<<<gproj, blk, PJ_SMEM>>>(Nb, Wh, Wl, bq, bk, bv, Qb, Kb, V);

    // 2. Scores (fp16 MMA) -> E = exp(score/16) bf16 + rowsum partials.
    dim3 gsc(kS / 256, kS / 128, kB);
    score_gemm<<<gsc, blk, SC_SMEM>>>(Qb, Kb, mask, E, rpart, 0.0625f);

    // 3. colsum (inline invr), w-reduce + output contraction over V.
    colsum_stream_kernel<<<dim3(QCH, kB), blk>>>(E, rpart, wpart);
    out_part_kernel<<<dim3(N_KCHUNK, kB), blk>>>(wpart, V, opart);
    out_reduce_kernel<<<(kB * kD) / 256, blk>>>(opart, out);
}

// round 15
// speedup vs baseline: 1.4789x; 1.1083x over previous
#include <cuda_runtime.h>
#include <cuda_bf16.h>
#include <cuda_fp16.h>
#include <cstdint>
#include <math.h>

// ---------------------------------------------------------------------------
// Problem constants
// ---------------------------------------------------------------------------
static constexpr int kB = 8;
static constexpr int kS = 2048;
static constexpr int kD = 256;
static constexpr int kM = kB * kS;
static constexpr int QCH = 64;       // colsum: 32 rows per chunk
static constexpr int N_KCHUNK = 32;  // output split over keys
static constexpr int NXT = kS / 256; // 8 n-tiles per batch row

// Scratch (static device memory)
// fp16 blocked layout: block = [128 rows x 64 cols] = 16KB, SW128-swizzled.
// Block id within a tensor = gmtile*4 + kchunk (kchunk of 64 cols).
__device__ __half g_Nb[kM * kD];                       // fp16 nodes, blocked
__device__ __half g_Wh[3 * kD * kD];                   // weight hi fp16 (q,k,v)
__device__ __half g_Wl[2 * kD * kD];                   // weight lo fp16 (q,k)
__device__ __half g_Qb[kB * kS * kD];                  // fp16 q, blocked
__device__ __half g_Kb[kB * kS * kD];                  // fp16 k, blocked
__device__ __half g_V[kB * kS * kD];                   // fp16 v, row-major
__device__ __nv_bfloat16 g_E[(size_t)kB * kS * kS];    // exp scores (bf16)
__device__ float g_rpart[NXT * kB * kS];
__device__ float g_wpart[QCH * kB * kS];
__device__ float g_opart[N_KCHUNK * kB * kD];

#if defined(__CUDA_ARCH__) && defined(__CUDA_ARCH_FEAT_SM103_ALL)
#define HAS_TCGEN05 1
#else
#define HAS_TCGEN05 0
#endif

#define SMEM_SWIZZLE_128B(byte_offset) \
    ((byte_offset) ^ (((byte_offset) >> 3) & 0x70))

__device__ __forceinline__ uint32_t smem_to_u32_gen(const void* p) {
    uint32_t a;
    asm("{ .reg .u64 t; cvta.to.shared.u64 t, %1; cvt.u32.u64 %0, t; }"
        : "=r"(a) : "l"(p));
    return a;
}

__device__ __forceinline__ uint32_t pack_bf16x2(float lo, float hi) {
    uint32_t r;
    asm("cvt.rn.bf16x2.f32 %0, %1, %2;" : "=r"(r) : "f"(hi), "f"(lo));
    return r;
}

__device__ __forceinline__ uint32_t pack_f16x2(float lo, float hi) {
    uint32_t r;
    asm("cvt.rn.f16x2.f32 %0, %1, %2;" : "=r"(r) : "f"(hi), "f"(lo));
    return r;
}

// fp16 blocked: BYTE offset of element (col in [0,256), row r in [0,128))
__device__ __forceinline__ size_t qk16_byte_off(int gmtile, int col, int r) {
    uint32_t base = (uint32_t)(r * 128 + ((col & 63) >> 3) * 16);
    uint32_t sw = SMEM_SWIZZLE_128B(base) + (uint32_t)(col & 7) * 2;
    return ((size_t)(gmtile * 4 + (col >> 6)) << 14) + sw;
}

#if HAS_TCGEN05
__device__ __forceinline__ uint32_t elect_one_pred() {
    uint32_t pred;
    asm volatile(
        "{\n\t.reg .pred p;\n\t"
        "elect.sync _|p, 0xFFFFFFFF;\n\t"
        "selp.b32 %0, 1, 0, p;\n\t}"
        : "=r"(pred));
    return pred;
}

#define TCGEN05_ALLOC(smem_result_addr, nCols) \
    asm volatile("tcgen05.alloc.cta_group::1.sync.aligned.shared::cta.b32 [%0], %1;" \
                 :: "r"((uint32_t)(smem_result_addr)), "r"((uint32_t)(nCols)) : "memory")
#define TCGEN05_DEALLOC(tmem_addr, nCols) \
    asm volatile("tcgen05.dealloc.cta_group::1.sync.aligned.b32 %0, %1;" \
                 :: "r"(tmem_addr), "r"((uint32_t)(nCols)))
#define TCGEN05_RELINQUISH() \
    asm volatile("tcgen05.relinquish_alloc_permit.cta_group::1.sync.aligned;")
#define TCGEN05_COMMIT(mbar_smem_addr) \
    asm volatile("tcgen05.commit.cta_group::1.mbarrier::arrive::one.shared::cluster.b64 [%0];" \
                 :: "r"((uint32_t)(mbar_smem_addr)) : "memory")
#define TCGEN05_FENCE_AFTER() \
    asm volatile("tcgen05.fence::after_thread_sync;" ::: "memory")
#define TCGEN05_WAIT_LD() \
    asm volatile("tcgen05.wait::ld.sync.aligned;" ::: "memory")
#define MBARRIER_INIT(mbar_smem_addr, count) \
    asm volatile("mbarrier.init.shared.b64 [%0], %1;" \
                 :: "r"((uint32_t)(mbar_smem_addr)), "r"((uint32_t)(count)) : "memory")
#define MBARRIER_EXPECT_TX(mbar_smem_addr, tx_bytes) \
    asm volatile("mbarrier.arrive.expect_tx.shared.b64 _, [%0], %1;" \
                 :: "r"((uint32_t)(mbar_smem_addr)), "r"((uint32_t)(tx_bytes)) : "memory")

#define MBARRIER_WAIT_PARITY(mbar_smem_addr, phase_parity) do { \
    uint32_t _mbar = (uint32_t)(mbar_smem_addr); \
    uint32_t _parity = (uint32_t)(phase_parity); \
    uint32_t _done; \
    asm volatile( \
        "{\n\t.reg .pred p;\n\t" \
        "mbarrier.try_wait.parity.acquire.cta.shared::cta.b64 p, [%1], %2;\n\t" \
        "selp.b32 %0, 1, 0, p;\n\t}" \
        : "=r"(_done) : "r"(_mbar), "r"(_parity) : "memory"); \
    if (!_done) { \
        asm volatile( \
            "{\n\t.reg .pred P1;\n\t" \
            "WAIT_LOOP_%=:\n\t" \
            "mbarrier.try_wait.parity.acquire.cta.shared::cta.b64 P1, [%0], %1, 0x989680;\n\t" \
            "@P1 bra.uni WAIT_DONE_%=;\n\t" \
            "bra.uni WAIT_LOOP_%=;\n\t" \
            "WAIT_DONE_%=:\n\t}" \
            :: "r"(_mbar), "r"(_parity) : "memory"); \
    } \
} while(0)

#define TCGEN05_LD_32X32B_X32(r, tmem_addr) \
    asm volatile( \
        "tcgen05.ld.sync.aligned.32x32b.x32.b32 " \
        "{%0, %1, %2, %3, %4, %5, %6, %7, " \
        " %8, %9, %10, %11, %12, %13, %14, %15, " \
        " %16, %17, %18, %19, %20, %21, %22, %23, " \
        " %24, %25, %26, %27, %28, %29, %30, %31}, [%32];" \
        : "=r"((r)[0]),  "=r"((r)[1]),  "=r"((r)[2]),  "=r"((r)[3]), \
          "=r"((r)[4]),  "=r"((r)[5]),  "=r"((r)[6]),  "=r"((r)[7]), \
          "=r"((r)[8]),  "=r"((r)[9]),  "=r"((r)[10]), "=r"((r)[11]), \
          "=r"((r)[12]), "=r"((r)[13]), "=r"((r)[14]), "=r"((r)[15]), \
          "=r"((r)[16]), "=r"((r)[17]), "=r"((r)[18]), "=r"((r)[19]), \
          "=r"((r)[20]), "=r"((r)[21]), "=r"((r)[22]), "=r"((r)[23]), \
          "=r"((r)[24]), "=r"((r)[25]), "=r"((r)[26]), "=r"((r)[27]), \
          "=r"((r)[28]), "=r"((r)[29]), "=r"((r)[30]), "=r"((r)[31]) \
        : "r"(tmem_addr))

#define TCGEN05_MMA_F16_SS(d_tmem, a_desc, b_desc, idesc, enable_d) do { \
    uint32_t _en = (enable_d) ? 1u : 0u; \
    uint32_t _zero = 0u; \
    asm volatile( \
        "{\n\t.reg .pred p;\n\t" \
        "setp.ne.u32 p, %5, 0;\n\t" \
        "tcgen05.mma.cta_group::1.kind::f16 [%0], %1, %2, %3, {%4, %4, %4, %4}, p;\n\t" \
        "}" \
        :: "r"(d_tmem), "l"(a_desc), "l"(b_desc), "r"(idesc), "r"(_zero), "r"(_en) \
        : "memory"); \
} while(0)

static constexpr uint64_t SMEM_DESC_BASE_SW128 =
    (uint64_t(2)  << 61) | (uint64_t(1) << 46) | (uint64_t(64) << 32) | (uint64_t(1) << 16);
#define MAKE_SMEM_DESC(base_addr) \
    (SMEM_DESC_BASE_SW128 | ((uint64_t)((base_addr) >> 4) & 0x3FFF))

#define CP_ASYNC_BULK(dst_smem, src_gmem, bytes, mbar) \
    asm volatile("cp.async.bulk.shared::cta.global.mbarrier::complete_tx::bytes " \
                 "[%0], [%1], %2, [%3];" \
                 :: "r"((uint32_t)(dst_smem)), "l"(src_gmem), \
                    "r"((uint32_t)(bytes)), "r"((uint32_t)(mbar)) : "memory")

// IDESCs (F32 accum, fp16 operands)
static constexpr uint32_t IDESC_F16_128x128 =
    (1u << 4) | (0u << 7) | (0u << 10) | ((128 / 8) << 17) | ((128 / 16) << 24);
static constexpr uint32_t IDESC_F16_128x256 =
    (1u << 4) | (0u << 7) | (0u << 10) | ((256 / 8) << 17) | ((128 / 16) << 24);
#endif  // HAS_TCGEN05

// ---------------------------------------------------------------------------
// Prep 1: nodes -> fp16 blocked. grid (4 kc, kM/128).
// ---------------------------------------------------------------------------
__global__ __launch_bounds__(256)
void nodes_prep(const float* __restrict__ src, __half* __restrict__ Nb)
{
    const int kc = blockIdx.x;
    const int mt = blockIdx.y;
    const int tid = threadIdx.x;
    char* blk = (char*)(Nb + (((size_t)mt * 4 + kc) << 13));
#pragma unroll
    for (int t = 0; t < 4; t++) {
        int idx = tid + t * 256;
        int row = idx >> 3, j = idx & 7;          // j: 8-col group
        const float* s = src + (size_t)(mt * 128 + row) * kD + kc * 64 + j * 8;
        float4 a = *(const float4*)s;
        float4 b = *(const float4*)(s + 4);
        uint32_t pk[4];
        pk[0] = pack_f16x2(a.x, a.y);
        pk[1] = pack_f16x2(a.z, a.w);
        pk[2] = pack_f16x2(b.x, b.y);
        pk[3] = pack_f16x2(b.z, b.w);
        uint32_t sw = SMEM_SWIZZLE_128B((uint32_t)(row * 128 + j * 16));
        *(uint4*)(blk + sw) = *(uint4*)pk;
    }
}

// ---------------------------------------------------------------------------
// Prep 2: weights -> fp16 (hi, lo) split, blocked. grid (4 kc, 2 mt, 3 w).
// ---------------------------------------------------------------------------
__global__ __launch_bounds__(256)
void wsplit_prep(const float* __restrict__ Wq, const float* __restrict__ Wk,
                 const float* __restrict__ Wv,
                 __half* __restrict__ Wh, __half* __restrict__ Wl)
{
    const int kc = blockIdx.x;
    const int mt = blockIdx.y;
    const int w  = blockIdx.z;
    const int tid = threadIdx.x;
    const float* W = (w == 0) ? Wq : (w == 1) ? Wk : Wv;
    char* bh = (char*)(Wh + (size_t)w * (kD * kD) + (((size_t)mt * 4 + kc) << 13));
    char* bl = (w < 2)
        ? (char*)(Wl + (size_t)w * (kD * kD) + (((size_t)mt * 4 + kc) << 13))
        : nullptr;
#pragma unroll
    for (int t = 0; t < 4; t++) {
        int idx = tid + t * 256;
        int row = idx >> 3, j = idx & 7;
        const float* s = W + (size_t)(mt * 128 + row) * kD + kc * 64 + j * 8;
        float x[8];
        *(float4*)&x[0] = *(const float4*)s;
        *(float4*)&x[4] = *(const float4*)(s + 4);
        float h[8], l[8];
#pragma unroll
        for (int i = 0; i < 8; i++) {
            h[i] = __half2float(__float2half_rn(x[i]));
            l[i] = x[i] - h[i];
        }
        uint32_t pkh[4], pkl[4];
#pragma unroll
        for (int i = 0; i < 4; i++) {
            pkh[i] = pack_f16x2(h[i * 2], h[i * 2 + 1]);
            pkl[i] = pack_f16x2(l[i * 2], l[i * 2 + 1]);
        }
        uint32_t sw = SMEM_SWIZZLE_128B((uint32_t)(row * 128 + j * 16));
        *(uint4*)(bh + sw) = *(uint4*)pkh;
        if (bl) *(uint4*)(bl + sw) = *(uint4*)pkl;
    }
}

// ---------------------------------------------------------------------------
// Pipelined fp16 projection GEMM, BM=128, BN=128, grid (2 nx, 128 my, 3 w).
//   q/k (w<2): C = fp16( A @ (Wh+Wl)^T + bias ) -> fp16 blocked
//   v  (w=2): C = fp16( A @ Wh^T + bias )       -> fp16 row-major
// 4 chunks of K=64. Stage: A 16K | Wh 16K | Wl 16K.
// ---------------------------------------------------------------------------
static constexpr int PJ_STAGE = 49152;
static constexpr int PJ_SMEM = 2048 + 2 * PJ_STAGE;   // 100352

__global__ __launch_bounds__(256)
void proj_gemm(const __half* __restrict__ Nb,
               const __half* __restrict__ Wh, const __half* __restrict__ Wl,
               const float* __restrict__ b0, const float* __restrict__ b1,
               const float* __restrict__ b2,
               __half* __restrict__ C0, __half* __restrict__ C1,
               __half* __restrict__ C2)
{
    extern __shared__ __align__(1024) char smem[];
    const int tid = threadIdx.x;
    const int nx = blockIdx.x;
    const int my = blockIdx.y;
    const int w  = blockIdx.z;
    const float* bias = (w == 0) ? b0 : (w == 1) ? b1 : b2;
    const bool two_pass = (w < 2);
    __half* Ch = (w == 0) ? C0 : (w == 1) ? C1 : C2;
    const char* WhB = (const char*)(Wh + (size_t)w * (kD * kD));
    const char* WlB = (const char*)(Wl + (size_t)w * (kD * kD));
    const char* NbB = (const char*)Nb;
    const int bn = nx * 128;
    const int bm = my * 128;

#if HAS_TCGEN05
    const uint32_t sb = smem_to_u32_gen(smem);
    const uint32_t m_done = sb + 32;
    float* s_bias = (float*)(smem + 1024);
    const int wid = tid >> 5;

    if (wid == 0) { TCGEN05_ALLOC(sb + 40, 128); TCGEN05_RELINQUISH(); }
    if (tid == 0) {
        MBARRIER_INIT(sb + 0, 1);
        MBARRIER_INIT(sb + 8, 1);
        MBARRIER_INIT(sb + 16, 1);
        MBARRIER_INIT(sb + 24, 1);
        MBARRIER_INIT(m_done, 1);
    }
    if (tid < 128) s_bias[tid] = bias[bn + tid];
    __syncthreads();
    const uint32_t tmem = *(volatile uint32_t*)(smem + 40);

    uint64_t dA[2], dBh[2], dBl[2];
#pragma unroll
    for (int s = 0; s < 2; s++) {
        uint32_t base = sb + 2048 + s * PJ_STAGE;
        dA[s]  = MAKE_SMEM_DESC(base);
        dBh[s] = MAKE_SMEM_DESC(base + 16384);
        dBl[s] = MAKE_SMEM_DESC(base + 32768);
    }

    const uint32_t tx_bytes = two_pass ? 49152u : 32768u;

    if (wid == 1) {
        if (elect_one_pred()) {
            for (int c = 0; c < 4; c++) {
                const int s = c & 1;
                const int i = c >> 1;
                const uint32_t m_full = sb + s * 8;
                const uint32_t m_emp  = sb + 16 + s * 8;
                const uint32_t st = sb + 2048 + s * PJ_STAGE;
                MBARRIER_WAIT_PARITY(m_emp, 1 ^ (i & 1));
                MBARRIER_EXPECT_TX(m_full, tx_bytes);
                CP_ASYNC_BULK(st,
                              NbB + (((size_t)my * 4 + c) << 14), 16384, m_full);
                CP_ASYNC_BULK(st + 16384,
                              WhB + (((size_t)nx * 4 + c) << 14), 16384, m_full);
                if (two_pass)
                    CP_ASYNC_BULK(st + 32768,
                                  WlB + (((size_t)nx * 4 + c) << 14), 16384, m_full);
            }
        }
    } else if (wid == 0) {
        if (elect_one_pred()) {
            for (int c = 0; c < 4; c++) {
                const int s = c & 1;
                const int i = c >> 1;
                const uint32_t m_full = sb + s * 8;
                const uint32_t m_emp  = sb + 16 + s * 8;
                MBARRIER_WAIT_PARITY(m_full, i & 1);
#pragma unroll
                for (int k = 0; k < 4; k++)     // 4 x K=16 fp16 steps, +32B each
                    TCGEN05_MMA_F16_SS(tmem, dA[s] + k * 2, dBh[s] + k * 2,
                                       IDESC_F16_128x128, (c > 0) || (k > 0));
                if (two_pass) {
#pragma unroll
                    for (int k = 0; k < 4; k++)
                        TCGEN05_MMA_F16_SS(tmem, dA[s] + k * 2, dBl[s] + k * 2,
                                           IDESC_F16_128x128, true);
                }
                TCGEN05_COMMIT(m_emp);
            }
            TCGEN05_COMMIT(m_done);
        }
    }

    MBARRIER_WAIT_PARITY(m_done, 0);
    TCGEN05_FENCE_AFTER();

    // Epilogue: warps 0-3 cols 0-63, warps 4-7 cols 64-127.
    {
        const int lane = tid & 31;
        const int half = wid >> 2;
        const int mloc = (wid & 3) * 32 + lane;
        const int m = bm + mloc;
#pragma unroll
        for (int g = 0; g < 2; g++) {
            const int col0 = half * 64 + g * 32;
            uint32_t r[32];
            TCGEN05_LD_32X32B_X32(r, tmem + col0);
            TCGEN05_WAIT_LD();
            float e[32];
#pragma unroll
            for (int j = 0; j < 32; j++)
                e[j] = __uint_as_float(r[j]) + s_bias[col0 + j];
            uint32_t pk[16];
#pragma unroll
            for (int j = 0; j < 16; j++)
                pk[j] = pack_f16x2(e[j * 2], e[j * 2 + 1]);
            if (two_pass) {
                // fp16 blocked: block = gmtile*4 + nx*2 + half
                __half* blk = Ch + (((size_t)(m >> 7) * 4 + nx * 2 + half) << 13);
#pragma unroll
                for (int j = 0; j < 4; j++) {
                    uint32_t sw = SMEM_SWIZZLE_128B(
                        (uint32_t)(mloc * 128 + g * 64 + j * 16));
                    *(uint4*)((char*)blk + sw) = *(uint4*)&pk[j * 4];
                }
            } else {
                // fp16 row-major
                __half* crow = Ch + (size_t)m * kD + bn + col0;
#pragma unroll
                for (int j = 0; j < 4; j++)
                    *(uint4*)&crow[j * 8] = *(uint4*)&pk[j * 4];
            }
        }
    }
    __syncthreads();
    if (wid == 0) TCGEN05_DEALLOC(tmem, 128);

#else
    // SIMT fallback — reads fp16 blocked Nb / Wh / Wl.
    constexpr int BK = 16, TM = 8, TN = 8;
    float* As = (float*)smem;
    float* Bs = As + BK * 128;
    const int tx = tid & 15, ty = tid >> 4;

    float acc[TM][TN];
#pragma unroll
    for (int i = 0; i < TM; i++)
#pragma unroll
        for (int j = 0; j < TN; j++) acc[i][j] = 0.0f;

    for (int k0 = 0; k0 < kD; k0 += BK) {
        __syncthreads();
        for (int li = tid; li < 128 * BK; li += 256) {
            int row = li / BK, kc = li % BK;
            size_t offA = qk16_byte_off(my, k0 + kc, row);
            size_t offB = qk16_byte_off(nx, k0 + kc, row);
            As[kc * 128 + row] = __half2float(*(const __half*)(NbB + offA));
            float bw = __half2float(*(const __half*)(WhB + offB));
            if (two_pass) bw += __half2float(*(const __half*)(WlB + offB));
            Bs[kc * 128 + row] = bw;
        }
        __syncthreads();
#pragma unroll
        for (int kk = 0; kk < BK; kk++) {
            float a[TM], bb[TN];
            *(float4*)&a[0]  = *(const float4*)&As[kk * 128 + ty * TM];
            *(float4*)&a[4]  = *(const float4*)&As[kk * 128 + ty * TM + 4];
            *(float4*)&bb[0] = *(const float4*)&Bs[kk * 128 + tx * TN];
            *(float4*)&bb[4] = *(const float4*)&Bs[kk * 128 + tx * TN + 4];
#pragma unroll
            for (int i = 0; i < TM; i++)
#pragma unroll
                for (int j = 0; j < TN; j++)
                    acc[i][j] = fmaf(a[i], bb[j], acc[i][j]);
        }
    }
    const int row0 = bm + ty * TM, col0 = bn + tx * TN;
#pragma unroll
    for (int i = 0; i < TM; i++)
#pragma unroll
        for (int j = 0; j < TN; j++) {
            float v = acc[i][j] + bias[col0 + j];
            int m = row0 + i, n = col0 + j;
            if (two_pass)
                *(__half*)((char*)Ch + qk16_byte_off(m >> 7, n, m & 127)) =
                    __float2half_rn(v);
            else
                Ch[(size_t)m * kD + n] = __float2half_rn(v);
        }
#endif
}

// ---------------------------------------------------------------------------
// Scores GEMM (fp16 inputs): E = exp((q.k)/16)*maskfac bf16 + rowsum partials.
// BM=128, BN=256. 4 K-chunks of 64 fp16, stages {Q 16K | K 32K} x2.
// grid (8 nx, 16 my, 8 bz), 2 CTAs/SM.   [unchanged from R14]
// ---------------------------------------------------------------------------
static constexpr int SC_STAGE = 49152;
static constexpr int SC_SMEM = 2048 + 2 * SC_STAGE;   // 100352

__global__ __launch_bounds__(256)
void score_gemm(const __half* __restrict__ Qb, const __half* __restrict__ Kb,
                const int* __restrict__ mask, __nv_bfloat16* __restrict__ E,
                float* __restrict__ rpart, float scale)
{
    extern __shared__ __align__(1024) char smem[];
    const int tid = threadIdx.x;
    const int bz = blockIdx.z;
    __nv_bfloat16* C = E + (size_t)bz * kS * kS;
    const int* mk = mask + (size_t)bz * kS;

    const int my = blockIdx.y;          // m tile (128 rows)
    const int nx = blockIdx.x;          // n tile (256 cols)
    const int bm = my * 128;
    const int bn = nx * 256;

#if HAS_TCGEN05
    const uint32_t sb = smem_to_u32_gen(smem);
    const uint32_t m_done = sb + 32;
    float* s_rs2 = (float*)(smem + 256);
    float* s_mf  = (float*)(smem + 1024);
    const int wid = tid >> 5;

    if (wid == 0) { TCGEN05_ALLOC(sb + 40, 256); TCGEN05_RELINQUISH(); }
    if (tid == 0) {
        MBARRIER_INIT(sb + 0, 1);
        MBARRIER_INIT(sb + 8, 1);
        MBARRIER_INIT(sb + 16, 1);
        MBARRIER_INIT(sb + 24, 1);
        MBARRIER_INIT(m_done, 1);
    }
    s_mf[tid] = (mk[bn + tid] != 0) ? 1.0f : 0.0f;
    __syncthreads();
    const uint32_t tmem = *(volatile uint32_t*)(smem + 40);

    uint64_t dA[2], dB[2];
#pragma unroll
    for (int s = 0; s < 2; s++) {
        uint32_t base = sb + 2048 + s * SC_STAGE;
        dA[s] = MAKE_SMEM_DESC(base);
        dB[s] = MAKE_SMEM_DESC(base + 16384);
    }

    const int amt  = bz * 16 + my;
    const int bmt0 = bz * 16 + nx * 2;

    if (wid == 1) {
        if (elect_one_pred()) {
            for (int c = 0; c < 4; c++) {      // 4 chunks of K=64 fp16
                const int s = c & 1;
                const int i = c >> 1;
                const uint32_t m_full = sb + s * 8;
                const uint32_t m_emp  = sb + 16 + s * 8;
                const uint32_t st = sb + 2048 + s * SC_STAGE;
                MBARRIER_WAIT_PARITY(m_emp, 1 ^ (i & 1));
                MBARRIER_EXPECT_TX(m_full, SC_STAGE);
                CP_ASYNC_BULK(st,
                              (const char*)Qb + (((size_t)amt * 4 + c) << 14),
                              16384, m_full);
                CP_ASYNC_BULK(st + 16384,
                              (const char*)Kb + (((size_t)bmt0 * 4 + c) << 14),
                              16384, m_full);
                CP_ASYNC_BULK(st + 32768,
                              (const char*)Kb + (((size_t)(bmt0 + 1) * 4 + c) << 14),
                              16384, m_full);
            }
        }
    } else if (wid == 0) {
        if (elect_one_pred()) {
            for (int c = 0; c < 4; c++) {
                const int s = c & 1;
                const int i = c >> 1;
                const uint32_t m_full = sb + s * 8;
                const uint32_t m_emp  = sb + 16 + s * 8;
                MBARRIER_WAIT_PARITY(m_full, i & 1);
#pragma unroll
                for (int k = 0; k < 4; k++)     // 4 x K=16 steps, +32B each
                    TCGEN05_MMA_F16_SS(tmem, dA[s] + k * 2, dB[s] + k * 2,
                                       IDESC_F16_128x256, (c > 0) || (k > 0));
                TCGEN05_COMMIT(m_emp);
            }
            TCGEN05_COMMIT(m_done);
        }
    }

    MBARRIER_WAIT_PARITY(m_done, 0);
    TCGEN05_FENCE_AFTER();

    // Epilogue: warps 0-3 keys 0-127, warps 4-7 keys 128-255 (same q rows).
    {
        const int lane = tid & 31;
        const int half = wid >> 2;
        const int qrow = (wid & 3) * 32 + lane;
        const int m = bm + qrow;
        __nv_bfloat16* crow = C + (size_t)m * kS + bn + half * 128;
        float rs = 0.0f;
#pragma unroll
        for (int g = 0; g < 4; g++) {
            const int col0 = half * 128 + g * 32;
            uint32_t r[32];
            TCGEN05_LD_32X32B_X32(r, tmem + col0);
            TCGEN05_WAIT_LD();
            float e[32];
#pragma unroll
            for (int j = 0; j < 32; j++) {
                e[j] = __expf(__uint_as_float(r[j]) * scale) * s_mf[col0 + j];
                rs += e[j];
            }
            uint32_t pk[16];
#pragma unroll
            for (int j = 0; j < 16; j++)
                pk[j] = pack_bf16x2(e[j * 2], e[j * 2 + 1]);
#pragma unroll
            for (int j = 0; j < 4; j++)
                *(uint4*)&crow[g * 32 + j * 8] = *(uint4*)&pk[j * 4];
        }
        if (half == 1) s_rs2[qrow] = rs;
        __syncthreads();
        if (half == 0)
            rpart[((size_t)nx * kB + bz) * kS + m] = rs + s_rs2[qrow];
    }
    __syncthreads();
    if (wid == 0) TCGEN05_DEALLOC(tmem, 256);

#else
    // SIMT fallback — reads fp16 blocked Q/K, writes bf16 E + rpart.
    constexpr int BK = 16, TM = 8, TN = 8;
    float* As = (float*)smem;
    float* Bs = As + BK * 128;
    const int tx = tid & 15, ty = tid >> 4;
    const int amt  = bz * 16 + my;
    const int bmt0 = bz * 16 + nx * 2;

    float rs[TM];
#pragma unroll
    for (int i = 0; i < TM; i++) rs[i] = 0.0f;

    for (int nh = 0; nh < 2; nh++) {
        const int bmtl = bmt0 + nh;
        float acc[TM][TN];
#pragma unroll
        for (int i = 0; i < TM; i++)
#pragma unroll
            for (int j = 0; j < TN; j++) acc[i][j] = 0.0f;

        for (int k0 = 0; k0 < kD; k0 += BK) {
            __syncthreads();
            for (int li = tid; li < 128 * BK; li += 256) {
                int row = li / BK, kc = li % BK;
                As[kc * 128 + row] = __half2float(*(const __half*)
                    ((const char*)Qb + qk16_byte_off(amt, k0 + kc, row)));
                Bs[kc * 128 + row] = __half2float(*(const __half*)
                    ((const char*)Kb + qk16_byte_off(bmtl, k0 + kc, row)));
            }
            __syncthreads();
#pragma unroll
            for (int kk = 0; kk < BK; kk++) {
                float a[TM], bb[TN];
                *(float4*)&a[0]  = *(const float4*)&As[kk * 128 + ty * TM];
                *(float4*)&a[4]  = *(const float4*)&As[kk * 128 + ty * TM + 4];
                *(float4*)&bb[0] = *(const float4*)&Bs[kk * 128 + tx * TN];
                *(float4*)&bb[4] = *(const float4*)&Bs[kk * 128 + tx * TN + 4];
#pragma unroll
                for (int i = 0; i < TM; i++)
#pragma unroll
                    for (int j = 0; j < TN; j++)
                        acc[i][j] = fmaf(a[i], bb[j], acc[i][j]);
            }
        }
        const int row0 = bm + ty * TM;
        const int col0 = bn + nh * 128 + tx * TN;
#pragma unroll
        for (int i = 0; i < TM; i++)
#pragma unroll
            for (int j = 0; j < TN; j++) {
                float e = __expf(acc[i][j] * scale)
                          * ((mk[col0 + j] != 0) ? 1.0f : 0.0f);
                C[(size_t)(row0 + i) * kS + col0 + j] = __float2bfloat16(e);
                rs[i] += e;
            }
        __syncthreads();
    }
#pragma unroll
    for (int i = 0; i < TM; i++) {
        float v = rs[i];
#pragma unroll
        for (int o = 8; o; o >>= 1) v += __shfl_xor_sync(0xffffffffu, v, o);
        if (tx == 0)
            rpart[((size_t)nx * kB + bz) * kS + bm + ty * TM + i] = v;
    }
#endif
}

// ---------------------------------------------------------------------------
// Column-sum stream over bf16 E with inline invr (from rpart partials).
// ---------------------------------------------------------------------------
__global__ __launch_bounds__(256)
void colsum_stream_kernel(const __nv_bfloat16* __restrict__ E,
                          const float* __restrict__ rpart,
                          float* __restrict__ wpart)
{
    __shared__ float s_inv[32];
    const int ch = blockIdx.x;
    const int b  = blockIdx.y;
    const int tid = threadIdx.x;

    if (tid < 32) {
        const size_t q = (size_t)b * kS + (size_t)ch * 32 + tid;
        float s = 0.0f;
#pragma unroll
        for (int c = 0; c < NXT; c++) s += rpart[(size_t)c * (kB * kS) + q];
        s_inv[tid] = 1.0f / s;
    }
    __syncthreads();

    const __nv_bfloat16* base = E + ((size_t)b * kS + (size_t)ch * 32) * kS;
    float wacc[8];
#pragma unroll
    for (int i = 0; i < 8; i++) wacc[i] = 0.0f;

    for (int r = 0; r < 32; r++) {
        const float s = s_inv[r];
        const __nv_bfloat16* p = base + (size_t)r * kS + tid * 8;
        uint4 v = *(const uint4*)p;
        const uint32_t pk[4] = {v.x, v.y, v.z, v.w};
#pragma unroll
        for (int i = 0; i < 4; i++) {
            float2 f = __bfloat1622float2(*(const __nv_bfloat162*)&pk[i]);
            wacc[i * 2]     = fmaf(f.x, s, wacc[i * 2]);
            wacc[i * 2 + 1] = fmaf(f.y, s, wacc[i * 2 + 1]);
        }
    }

    float* o = wpart + (size_t)ch * (kB * kS) + (size_t)b * kS + tid * 8;
    *(float4*)&o[0] = make_float4(wacc[0], wacc[1], wacc[2], wacc[3]);
    *(float4*)&o[4] = make_float4(wacc[4], wacc[5], wacc[6], wacc[7]);
}

// ---------------------------------------------------------------------------
// out_part: w segment reduced from wpart in-block, then o = sum_k w_k V[k,d].
// V is fp16 row-major.
// ---------------------------------------------------------------------------
__global__ __launch_bounds__(256)
void out_part_kernel(const float* __restrict__ wpart, const __half* __restrict__ V,
                     float* __restrict__ opart)
{
    __shared__ float ws[64];
    const int chunk = blockIdx.x;
    const int b     = blockIdx.y;
    const int tid   = threadIdx.x;

    if (tid < 64) {
        const int key = chunk * 64 + tid;
        float s = 0.0f;
#pragma unroll 8
        for (int c = 0; c < QCH; c++)
            s += wpart[(size_t)c * (kB * kS) + (size_t)b * kS + key];
        ws[tid] = s;
    }
    __syncthreads();

    const __half* vb = V + ((size_t)b * kS + (size_t)chunk * 64) * kD;
    float s = 0.0f;
#pragma unroll
    for (int k = 0; k < 64; k++)
        s = fmaf(ws[k], __half2float(vb[(size_t)k * kD + tid]), s);
    opart[(size_t)(chunk * kB + b) * kD + tid] = s;
}

__global__ __launch_bounds__(256)
void out_reduce_kernel(const float* __restrict__ opart, float* __restrict__ out)
{
    const int i = blockIdx.x * 256 + threadIdx.x;
    float s = 0.0f;
#pragma unroll
    for (int c = 0; c < N_KCHUNK; c++) s += opart[(size_t)c * (kB * kD) + i];
    out[i] = s * (1.0f / (float)kS);
}

// ---------------------------------------------------------------------------
// Launch
// ---------------------------------------------------------------------------
extern "C" void kernel_launch(void* const* d_in, const int* in_sizes, int n_in,
                              void* d_out, int out_size)
{
    const float* nodes = (const float*)d_in[0];
    const int*   mask  = (const int*)  d_in[1];
    const float* Wq    = (const float*)d_in[2];
    const float* bq    = (const float*)d_in[3];
    const float* Wk    = (const float*)d_in[4];
    const float* bk    = (const float*)d_in[5];
    const float* Wv    = (const float*)d_in[6];
    const float* bv    = (const float*)d_in[7];
    float* out = (float*)d_out;

    float *rpart, *wpart, *opart;
    __half *Nb, *Wh, *Wl, *Qb, *Kb, *V;
    __nv_bfloat16* E;
    cudaGetSymbolAddress((void**)&Nb,    g_Nb);
    cudaGetSymbolAddress((void**)&Wh,    g_Wh);
    cudaGetSymbolAddress((void**)&Wl,    g_Wl);
    cudaGetSymbolAddress((void**)&Qb,    g_Qb);
    cudaGetSymbolAddress((void**)&Kb,    g_Kb);
    cudaGetSymbolAddress((void**)&V,     g_V);
    cudaGetSymbolAddress((void**)&E,     g_E);
    cudaGetSymbolAddress((void**)&rpart, g_rpart);
    cudaGetSymbolAddress((void**)&wpart, g_wpart);
    cudaGetSymbolAddress((void**)&opart, g_opart);

    cudaFuncSetAttribute(proj_gemm,
                         cudaFuncAttributeMaxDynamicSharedMemorySize, PJ_SMEM);
    cudaFuncSetAttribute(score_gemm,
                         cudaFuncAttributeMaxDynamicSharedMemorySize, SC_SMEM);

    dim3 blk(256);

    // 0. Prep: nodes -> fp16 blocked; weights -> fp16 hi/lo blocked.
    nodes_prep<<<dim3(4, kM / 128), blk>>>(nodes, Nb);
    wsplit_prep<<<dim3(4, 2, 3), blk>>>(Wq, Wk, Wv, Wh, Wl);

    // 1. Projections (fp16 MMA): grid (2 nx, 128 my, 3 w), 2 CTAs/SM.
    dim3 gproj(2, kM / 128, 3);
    proj_gemm<<<gproj, blk, PJ_SMEM>>>(Nb, Wh, Wl, bq, bk, bv, Qb, Kb, V);

    // 2. Scores (fp16 MMA) -> E = exp(score/16) bf16 + rowsum partials.
    dim3 gsc(kS / 256, kS / 128, kB);
    score_gemm<<<gsc, blk, SC_SMEM>>>(Qb, Kb, mask, E, rpart, 0.0625f);

    // 3. colsum (inline invr), w-reduce + output contraction over fp16 V.
    colsum_stream_kernel<<<dim3(QCH, kB), blk>>>(E, rpart, wpart);
    out_part_kernel<<<dim3(N_KCHUNK, kB), blk>>>(wpart, V, opart);
    out_reduce_kernel<<<(kB * kD) / 256, blk>>>(opart, out);
}

// round 16
// speedup vs baseline: 1.4998x; 1.0142x over previous
#include <cuda_runtime.h>
#include <cuda_bf16.h>
#include <cuda_fp16.h>
#include <cstdint>
#include <math.h>

// ---------------------------------------------------------------------------
// Problem constants
// ---------------------------------------------------------------------------
static constexpr int kB = 8;
static constexpr int kS = 2048;
static constexpr int kD = 256;
static constexpr int kM = kB * kS;
static constexpr int QCH = 64;       // colsum: 32 rows per chunk
static constexpr int N_KCHUNK = 32;  // output split over keys
static constexpr int NXT = kS / 256; // 8 n-tiles per batch row
static constexpr int NTILES = kB * (kS / 128) * (kS / 256);  // 1024

// Scratch (static device memory)
// fp16 blocked layout: block = [128 rows x 64 cols] = 16KB, SW128-swizzled.
__device__ __half g_Nb[kM * kD];                       // fp16 nodes, blocked
__device__ __half g_Wh[3 * kD * kD];                   // weight hi fp16 (q,k,v)
__device__ __half g_Wl[2 * kD * kD];                   // weight lo fp16 (q,k)
__device__ __half g_Qb[kB * kS * kD];                  // fp16 q, blocked
__device__ __half g_Kb[kB * kS * kD];                  // fp16 k, blocked
__device__ __half g_V[kB * kS * kD];                   // fp16 v, row-major
__device__ float  g_maskf[kB * kS];                    // 1.0 / 0.0 mask factors
__device__ __nv_bfloat16 g_E[(size_t)kB * kS * kS];    // exp scores (bf16)
__device__ float g_rpart[NXT * kB * kS];
__device__ float g_wpart[QCH * kB * kS];
__device__ float g_opart[N_KCHUNK * kB * kD];

#if defined(__CUDA_ARCH__) && defined(__CUDA_ARCH_FEAT_SM103_ALL)
#define HAS_TCGEN05 1
#else
#define HAS_TCGEN05 0
#endif

#define SMEM_SWIZZLE_128B(byte_offset) \
    ((byte_offset) ^ (((byte_offset) >> 3) & 0x70))

__device__ __forceinline__ uint32_t smem_to_u32_gen(const void* p) {
    uint32_t a;
    asm("{ .reg .u64 t; cvta.to.shared.u64 t, %1; cvt.u32.u64 %0, t; }"
        : "=r"(a) : "l"(p));
    return a;
}

__device__ __forceinline__ uint32_t pack_bf16x2(float lo, float hi) {
    uint32_t r;
    asm("cvt.rn.bf16x2.f32 %0, %1, %2;" : "=r"(r) : "f"(hi), "f"(lo));
    return r;
}

__device__ __forceinline__ uint32_t pack_f16x2(float lo, float hi) {
    uint32_t r;
    asm("cvt.rn.f16x2.f32 %0, %1, %2;" : "=r"(r) : "f"(hi), "f"(lo));
    return r;
}

// fp16 blocked: BYTE offset of element (col in [0,256), row r in [0,128))
__device__ __forceinline__ size_t qk16_byte_off(int gmtile, int col, int r) {
    uint32_t base = (uint32_t)(r * 128 + ((col & 63) >> 3) * 16);
    uint32_t sw = SMEM_SWIZZLE_128B(base) + (uint32_t)(col & 7) * 2;
    return ((size_t)(gmtile * 4 + (col >> 6)) << 14) + sw;
}

#if HAS_TCGEN05
__device__ __forceinline__ uint32_t elect_one_pred() {
    uint32_t pred;
    asm volatile(
        "{\n\t.reg .pred p;\n\t"
        "elect.sync _|p, 0xFFFFFFFF;\n\t"
        "selp.b32 %0, 1, 0, p;\n\t}"
        : "=r"(pred));
    return pred;
}

#define TCGEN05_ALLOC(smem_result_addr, nCols) \
    asm volatile("tcgen05.alloc.cta_group::1.sync.aligned.shared::cta.b32 [%0], %1;" \
                 :: "r"((uint32_t)(smem_result_addr)), "r"((uint32_t)(nCols)) : "memory")
#define TCGEN05_DEALLOC(tmem_addr, nCols) \
    asm volatile("tcgen05.dealloc.cta_group::1.sync.aligned.b32 %0, %1;" \
                 :: "r"(tmem_addr), "r"((uint32_t)(nCols)))
#define TCGEN05_RELINQUISH() \
    asm volatile("tcgen05.relinquish_alloc_permit.cta_group::1.sync.aligned;")
#define TCGEN05_COMMIT(mbar_smem_addr) \
    asm volatile("tcgen05.commit.cta_group::1.mbarrier::arrive::one.shared::cluster.b64 [%0];" \
                 :: "r"((uint32_t)(mbar_smem_addr)) : "memory")
#define TCGEN05_FENCE_AFTER() \
    asm volatile("tcgen05.fence::after_thread_sync;" ::: "memory")
#define TCGEN05_FENCE_BEFORE() \
    asm volatile("tcgen05.fence::before_thread_sync;" ::: "memory")
#define TCGEN05_WAIT_LD() \
    asm volatile("tcgen05.wait::ld.sync.aligned;" ::: "memory")
#define MBARRIER_INIT(mbar_smem_addr, count) \
    asm volatile("mbarrier.init.shared.b64 [%0], %1;" \
                 :: "r"((uint32_t)(mbar_smem_addr)), "r"((uint32_t)(count)) : "memory")
#define MBARRIER_ARRIVE(mbar_smem_addr) \
    asm volatile("mbarrier.arrive.shared.b64 _, [%0];" \
                 :: "r"((uint32_t)(mbar_smem_addr)) : "memory")
#define MBARRIER_EXPECT_TX(mbar_smem_addr, tx_bytes) \
    asm volatile("mbarrier.arrive.expect_tx.shared.b64 _, [%0], %1;" \
                 :: "r"((uint32_t)(mbar_smem_addr)), "r"((uint32_t)(tx_bytes)) : "memory")

#define MBARRIER_WAIT_PARITY(mbar_smem_addr, phase_parity) do { \
    uint32_t _mbar = (uint32_t)(mbar_smem_addr); \
    uint32_t _parity = (uint32_t)(phase_parity); \
    uint32_t _done; \
    asm volatile( \
        "{\n\t.reg .pred p;\n\t" \
        "mbarrier.try_wait.parity.acquire.cta.shared::cta.b64 p, [%1], %2;\n\t" \
        "selp.b32 %0, 1, 0, p;\n\t}" \
        : "=r"(_done) : "r"(_mbar), "r"(_parity) : "memory"); \
    if (!_done) { \
        asm volatile( \
            "{\n\t.reg .pred P1;\n\t" \
            "WAIT_LOOP_%=:\n\t" \
            "mbarrier.try_wait.parity.acquire.cta.shared::cta.b64 P1, [%0], %1, 0x989680;\n\t" \
            "@P1 bra.uni WAIT_DONE_%=;\n\t" \
            "bra.uni WAIT_LOOP_%=;\n\t" \
            "WAIT_DONE_%=:\n\t}" \
            :: "r"(_mbar), "r"(_parity) : "memory"); \
    } \
} while(0)

#define TCGEN05_LD_32X32B_X32(r, tmem_addr) \
    asm volatile( \
        "tcgen05.ld.sync.aligned.32x32b.x32.b32 " \
        "{%0, %1, %2, %3, %4, %5, %6, %7, " \
        " %8, %9, %10, %11, %12, %13, %14, %15, " \
        " %16, %17, %18, %19, %20, %21, %22, %23, " \
        " %24, %25, %26, %27, %28, %29, %30, %31}, [%32];" \
        : "=r"((r)[0]),  "=r"((r)[1]),  "=r"((r)[2]),  "=r"((r)[3]), \
          "=r"((r)[4]),  "=r"((r)[5]),  "=r"((r)[6]),  "=r"((r)[7]), \
          "=r"((r)[8]),  "=r"((r)[9]),  "=r"((r)[10]), "=r"((r)[11]), \
          "=r"((r)[12]), "=r"((r)[13]), "=r"((r)[14]), "=r"((r)[15]), \
          "=r"((r)[16]), "=r"((r)[17]), "=r"((r)[18]), "=r"((r)[19]), \
          "=r"((r)[20]), "=r"((r)[21]), "=r"((r)[22]), "=r"((r)[23]), \
          "=r"((r)[24]), "=r"((r)[25]), "=r"((r)[26]), "=r"((r)[27]), \
          "=r"((r)[28]), "=r"((r)[29]), "=r"((r)[30]), "=r"((r)[31]) \
        : "r"(tmem_addr))

#define TCGEN05_MMA_F16_SS(d_tmem, a_desc, b_desc, idesc, enable_d) do { \
    uint32_t _en = (enable_d) ? 1u : 0u; \
    uint32_t _zero = 0u; \
    asm volatile( \
        "{\n\t.reg .pred p;\n\t" \
        "setp.ne.u32 p, %5, 0;\n\t" \
        "tcgen05.mma.cta_group::1.kind::f16 [%0], %1, %2, %3, {%4, %4, %4, %4}, p;\n\t" \
        "}" \
        :: "r"(d_tmem), "l"(a_desc), "l"(b_desc), "r"(idesc), "r"(_zero), "r"(_en) \
        : "memory"); \
} while(0)

static constexpr uint64_t SMEM_DESC_BASE_SW128 =
    (uint64_t(2)  << 61) | (uint64_t(1) << 46) | (uint64_t(64) << 32) | (uint64_t(1) << 16);
#define MAKE_SMEM_DESC(base_addr) \
    (SMEM_DESC_BASE_SW128 | ((uint64_t)((base_addr) >> 4) & 0x3FFF))

#define CP_ASYNC_BULK(dst_smem, src_gmem, bytes, mbar) \
    asm volatile("cp.async.bulk.shared::cta.global.mbarrier::complete_tx::bytes " \
                 "[%0], [%1], %2, [%3];" \
                 :: "r"((uint32_t)(dst_smem)), "l"(src_gmem), \
                    "r"((uint32_t)(bytes)), "r"((uint32_t)(mbar)) : "memory")

// IDESCs (F32 accum, fp16 operands)
static constexpr uint32_t IDESC_F16_128x128 =
    (1u << 4) | (0u << 7) | (0u << 10) | ((128 / 8) << 17) | ((128 / 16) << 24);
static constexpr uint32_t IDESC_F16_128x256 =
    (1u << 4) | (0u << 7) | (0u << 10) | ((256 / 8) << 17) | ((128 / 16) << 24);
#endif  // HAS_TCGEN05

// ---------------------------------------------------------------------------
// Prep 1: nodes -> fp16 blocked. grid (4 kc, kM/128).
// ---------------------------------------------------------------------------
__global__ __launch_bounds__(256)
void nodes_prep(const float* __restrict__ src, __half* __restrict__ Nb)
{
    const int kc = blockIdx.x;
    const int mt = blockIdx.y;
    const int tid = threadIdx.x;
    char* blk = (char*)(Nb + (((size_t)mt * 4 + kc) << 13));
#pragma unroll
    for (int t = 0; t < 4; t++) {
        int idx = tid + t * 256;
        int row = idx >> 3, j = idx & 7;
        const float* s = src + (size_t)(mt * 128 + row) * kD + kc * 64 + j * 8;
        float4 a = *(const float4*)s;
        float4 b = *(const float4*)(s + 4);
        uint32_t pk[4];
        pk[0] = pack_f16x2(a.x, a.y);
        pk[1] = pack_f16x2(a.z, a.w);
        pk[2] = pack_f16x2(b.x, b.y);
        pk[3] = pack_f16x2(b.z, b.w);
        uint32_t sw = SMEM_SWIZZLE_128B((uint32_t)(row * 128 + j * 16));
        *(uint4*)(blk + sw) = *(uint4*)pk;
    }
}

// ---------------------------------------------------------------------------
// Prep 2: weights -> fp16 (hi, lo) split, blocked. grid (4 kc, 2 mt, 3 w).
// ---------------------------------------------------------------------------
__global__ __launch_bounds__(256)
void wsplit_prep(const float* __restrict__ Wq, const float* __restrict__ Wk,
                 const float* __restrict__ Wv,
                 __half* __restrict__ Wh, __half* __restrict__ Wl)
{
    const int kc = blockIdx.x;
    const int mt = blockIdx.y;
    const int w  = blockIdx.z;
    const int tid = threadIdx.x;
    const float* W = (w == 0) ? Wq : (w == 1) ? Wk : Wv;
    char* bh = (char*)(Wh + (size_t)w * (kD * kD) + (((size_t)mt * 4 + kc) << 13));
    char* bl = (w < 2)
        ? (char*)(Wl + (size_t)w * (kD * kD) + (((size_t)mt * 4 + kc) << 13))
        : nullptr;
#pragma unroll
    for (int t = 0; t < 4; t++) {
        int idx = tid + t * 256;
        int row = idx >> 3, j = idx & 7;
        const float* s = W + (size_t)(mt * 128 + row) * kD + kc * 64 + j * 8;
        float x[8];
        *(float4*)&x[0] = *(const float4*)s;
        *(float4*)&x[4] = *(const float4*)(s + 4);
        float h[8], l[8];
#pragma unroll
        for (int i = 0; i < 8; i++) {
            h[i] = __half2float(__float2half_rn(x[i]));
            l[i] = x[i] - h[i];
        }
        uint32_t pkh[4], pkl[4];
#pragma unroll
        for (int i = 0; i < 4; i++) {
            pkh[i] = pack_f16x2(h[i * 2], h[i * 2 + 1]);
            pkl[i] = pack_f16x2(l[i * 2], l[i * 2 + 1]);
        }
        uint32_t sw = SMEM_SWIZZLE_128B((uint32_t)(row * 128 + j * 16));
        *(uint4*)(bh + sw) = *(uint4*)pkh;
        if (bl) *(uint4*)(bl + sw) = *(uint4*)pkl;
    }
}

// ---------------------------------------------------------------------------
// Prep 3: mask -> float factors. grid (kB).
// ---------------------------------------------------------------------------
__global__ __launch_bounds__(256)
void maskf_prep(const int* __restrict__ mask, float* __restrict__ maskf)
{
    const int b = blockIdx.x;
    const int tid = threadIdx.x;
#pragma unroll
    for (int t = 0; t < 8; t++) {
        int k = tid + t * 256;
        maskf[b * kS + k] = (mask[b * kS + k] != 0) ? 1.0f : 0.0f;
    }
}

// ---------------------------------------------------------------------------
// Pipelined fp16 projection GEMM, BM=128, BN=128, grid (2 nx, 128 my, 3 w).
// [unchanged from R15]
// ---------------------------------------------------------------------------
static constexpr int PJ_STAGE = 49152;
static constexpr int PJ_SMEM = 2048 + 2 * PJ_STAGE;   // 100352

__global__ __launch_bounds__(256)
void proj_gemm(const __half* __restrict__ Nb,
               const __half* __restrict__ Wh, const __half* __restrict__ Wl,
               const float* __restrict__ b0, const float* __restrict__ b1,
               const float* __restrict__ b2,
               __half* __restrict__ C0, __half* __restrict__ C1,
               __half* __restrict__ C2)
{
    extern __shared__ __align__(1024) char smem[];
    const int tid = threadIdx.x;
    const int nx = blockIdx.x;
    const int my = blockIdx.y;
    const int w  = blockIdx.z;
    const float* bias = (w == 0) ? b0 : (w == 1) ? b1 : b2;
    const bool two_pass = (w < 2);
    __half* Ch = (w == 0) ? C0 : (w == 1) ? C1 : C2;
    const char* WhB = (const char*)(Wh + (size_t)w * (kD * kD));
    const char* WlB = (const char*)(Wl + (size_t)w * (kD * kD));
    const char* NbB = (const char*)Nb;
    const int bn = nx * 128;
    const int bm = my * 128;

#if HAS_TCGEN05
    const uint32_t sb = smem_to_u32_gen(smem);
    const uint32_t m_done = sb + 32;
    float* s_bias = (float*)(smem + 1024);
    const int wid = tid >> 5;

    if (wid == 0) { TCGEN05_ALLOC(sb + 40, 128); TCGEN05_RELINQUISH(); }
    if (tid == 0) {
        MBARRIER_INIT(sb + 0, 1);
        MBARRIER_INIT(sb + 8, 1);
        MBARRIER_INIT(sb + 16, 1);
        MBARRIER_INIT(sb + 24, 1);
        MBARRIER_INIT(m_done, 1);
    }
    if (tid < 128) s_bias[tid] = bias[bn + tid];
    __syncthreads();
    const uint32_t tmem = *(volatile uint32_t*)(smem + 40);

    uint64_t dA[2], dBh[2], dBl[2];
#pragma unroll
    for (int s = 0; s < 2; s++) {
        uint32_t base = sb + 2048 + s * PJ_STAGE;
        dA[s]  = MAKE_SMEM_DESC(base);
        dBh[s] = MAKE_SMEM_DESC(base + 16384);
        dBl[s] = MAKE_SMEM_DESC(base + 32768);
    }

    const uint32_t tx_bytes = two_pass ? 49152u : 32768u;

    if (wid == 1) {
        if (elect_one_pred()) {
            for (int c = 0; c < 4; c++) {
                const int s = c & 1;
                const int i = c >> 1;
                const uint32_t m_full = sb + s * 8;
                const uint32_t m_emp  = sb + 16 + s * 8;
                const uint32_t st = sb + 2048 + s * PJ_STAGE;
                MBARRIER_WAIT_PARITY(m_emp, 1 ^ (i & 1));
                MBARRIER_EXPECT_TX(m_full, tx_bytes);
                CP_ASYNC_BULK(st,
                              NbB + (((size_t)my * 4 + c) << 14), 16384, m_full);
                CP_ASYNC_BULK(st + 16384,
                              WhB + (((size_t)nx * 4 + c) << 14), 16384, m_full);
                if (two_pass)
                    CP_ASYNC_BULK(st + 32768,
                                  WlB + (((size_t)nx * 4 + c) << 14), 16384, m_full);
            }
        }
    } else if (wid == 0) {
        if (elect_one_pred()) {
            for (int c = 0; c < 4; c++) {
                const int s = c & 1;
                const int i = c >> 1;
                const uint32_t m_full = sb + s * 8;
                const uint32_t m_emp  = sb + 16 + s * 8;
                MBARRIER_WAIT_PARITY(m_full, i & 1);
#pragma unroll
                for (int k = 0; k < 4; k++)
                    TCGEN05_MMA_F16_SS(tmem, dA[s] + k * 2, dBh[s] + k * 2,
                                       IDESC_F16_128x128, (c > 0) || (k > 0));
                if (two_pass) {
#pragma unroll
                    for (int k = 0; k < 4; k++)
                        TCGEN05_MMA_F16_SS(tmem, dA[s] + k * 2, dBl[s] + k * 2,
                                           IDESC_F16_128x128, true);
                }
                TCGEN05_COMMIT(m_emp);
            }
            TCGEN05_COMMIT(m_done);
        }
    }

    MBARRIER_WAIT_PARITY(m_done, 0);
    TCGEN05_FENCE_AFTER();

    {
        const int lane = tid & 31;
        const int half = wid >> 2;
        const int mloc = (wid & 3) * 32 + lane;
        const int m = bm + mloc;
#pragma unroll
        for (int g = 0; g < 2; g++) {
            const int col0 = half * 64 + g * 32;
            uint32_t r[32];
            TCGEN05_LD_32X32B_X32(r, tmem + col0);
            TCGEN05_WAIT_LD();
            float e[32];
#pragma unroll
            for (int j = 0; j < 32; j++)
                e[j] = __uint_as_float(r[j]) + s_bias[col0 + j];
            uint32_t pk[16];
#pragma unroll
            for (int j = 0; j < 16; j++)
                pk[j] = pack_f16x2(e[j * 2], e[j * 2 + 1]);
            if (two_pass) {
                __half* blk = Ch + (((size_t)(m >> 7) * 4 + nx * 2 + half) << 13);
#pragma unroll
                for (int j = 0; j < 4; j++) {
                    uint32_t sw = SMEM_SWIZZLE_128B(
                        (uint32_t)(mloc * 128 + g * 64 + j * 16));
                    *(uint4*)((char*)blk + sw) = *(uint4*)&pk[j * 4];
                }
            } else {
                __half* crow = Ch + (size_t)m * kD + bn + col0;
#pragma unroll
                for (int j = 0; j < 4; j++)
                    *(uint4*)&crow[j * 8] = *(uint4*)&pk[j * 4];
            }
        }
    }
    __syncthreads();
    if (wid == 0) TCGEN05_DEALLOC(tmem, 128);

#else
    // SIMT fallback — reads fp16 blocked Nb / Wh / Wl.
    constexpr int BK = 16, TM = 8, TN = 8;
    float* As = (float*)smem;
    float* Bs = As + BK * 128;
    const int tx = tid & 15, ty = tid >> 4;

    float acc[TM][TN];
#pragma unroll
    for (int i = 0; i < TM; i++)
#pragma unroll
        for (int j = 0; j < TN; j++) acc[i][j] = 0.0f;

    for (int k0 = 0; k0 < kD; k0 += BK) {
        __syncthreads();
        for (int li = tid; li < 128 * BK; li += 256) {
            int row = li / BK, kc = li % BK;
            size_t offA = qk16_byte_off(my, k0 + kc, row);
            size_t offB = qk16_byte_off(nx, k0 + kc, row);
            As[kc * 128 + row] = __half2float(*(const __half*)(NbB + offA));
            float bw = __half2float(*(const __half*)(WhB + offB));
            if (two_pass) bw += __half2float(*(const __half*)(WlB + offB));
            Bs[kc * 128 + row] = bw;
        }
        __syncthreads();
#pragma unroll
        for (int kk = 0; kk < BK; kk++) {
            float a[TM], bb[TN];
            *(float4*)&a[0]  = *(const float4*)&As[kk * 128 + ty * TM];
            *(float4*)&a[4]  = *(const float4*)&As[kk * 128 + ty * TM + 4];
            *(float4*)&bb[0] = *(const float4*)&Bs[kk * 128 + tx * TN];
            *(float4*)&bb[4] = *(const float4*)&Bs[kk * 128 + tx * TN + 4];
#pragma unroll
            for (int i = 0; i < TM; i++)
#pragma unroll
                for (int j = 0; j < TN; j++)
                    acc[i][j] = fmaf(a[i], bb[j], acc[i][j]);
        }
    }
    const int row0 = bm + ty * TM, col0 = bn + tx * TN;
#pragma unroll
    for (int i = 0; i < TM; i++)
#pragma unroll
        for (int j = 0; j < TN; j++) {
            float v = acc[i][j] + bias[col0 + j];
            int m = row0 + i, n = col0 + j;
            if (two_pass)
                *(__half*)((char*)Ch + qk16_byte_off(m >> 7, n, m & 127)) =
                    __float2half_rn(v);
            else
                Ch[(size_t)m * kD + n] = __float2half_rn(v);
        }
#endif
}

// ---------------------------------------------------------------------------
// PERSISTENT scores kernel: grid 148 CTAs, 1/SM, each streams ~7 tiles.
// Tile = (bz, my, nx): 128 q rows x 256 keys. Per tile 4 K-chunks of 64 fp16.
// Warp roles: w1 elect = producer (bulk loads, 4-stage ring);
//             w0 elect = consumer (MMAs into TMEM double buffer D0/D1);
//             w2-5     = epilogue (exp, bf16 E store, rowsum) on finished D.
// smem ctrl: full[4]@0..24, empty[4]@32..56, mma_done[2]@64,72,
//            epi_done[2]@80,88 (count 128), tmem@96.
// stages: 4 x 48KB {Q 16K | K 32K} = 196608; total 198656 smem.
// ---------------------------------------------------------------------------
static constexpr int SC_STAGE = 49152;
static constexpr int SC_SMEM = 2048 + 4 * SC_STAGE;   // 198656
static constexpr int SC_GRID = 148;

__global__ __launch_bounds__(256)
void score_gemm(const __half* __restrict__ Qb, const __half* __restrict__ Kb,
                const float* __restrict__ maskf, __nv_bfloat16* __restrict__ E,
                float* __restrict__ rpart, float scale)
{
    extern __shared__ __align__(1024) char smem[];
    const int tid = threadIdx.x;

#if HAS_TCGEN05
    const uint32_t sb = smem_to_u32_gen(smem);
    const int wid = tid >> 5;
    const int lane = tid & 31;

    if (wid == 0) { TCGEN05_ALLOC(sb + 96, 512); TCGEN05_RELINQUISH(); }
    if (tid == 0) {
#pragma unroll
        for (int s = 0; s < 4; s++) {
            MBARRIER_INIT(sb + s * 8, 1);        // full[s]
            MBARRIER_INIT(sb + 32 + s * 8, 1);   // empty[s]
        }
        MBARRIER_INIT(sb + 64, 1);               // mma_done[0]
        MBARRIER_INIT(sb + 72, 1);               // mma_done[1]
        MBARRIER_INIT(sb + 80, 128);             // epi_done[0]
        MBARRIER_INIT(sb + 88, 128);             // epi_done[1]
    }
    __syncthreads();
    const uint32_t tmem = *(volatile uint32_t*)(smem + 96);

    uint64_t dA[4], dB[4];
#pragma unroll
    for (int s = 0; s < 4; s++) {
        uint32_t base = sb + 2048 + s * SC_STAGE;
        dA[s] = MAKE_SMEM_DESC(base);
        dB[s] = MAKE_SMEM_DESC(base + 16384);
    }

    if (wid == 1) {
        // -------- producer --------
        if (elect_one_pred()) {
            int g = 0;
            for (int t = blockIdx.x; t < NTILES; t += SC_GRID) {
                const int bz = t >> 7;
                const int my = (t & 127) >> 3;
                const int nx = t & 7;
                const int amt  = bz * 16 + my;
                const int bmt0 = bz * 16 + nx * 2;
                for (int c = 0; c < 4; c++, g++) {
                    const int s = g & 3;
                    const int u = g >> 2;
                    const uint32_t m_full = sb + s * 8;
                    const uint32_t m_emp  = sb + 32 + s * 8;
                    const uint32_t st = sb + 2048 + s * SC_STAGE;
                    MBARRIER_WAIT_PARITY(m_emp, 1 ^ (u & 1));
                    MBARRIER_EXPECT_TX(m_full, SC_STAGE);
                    CP_ASYNC_BULK(st,
                                  (const char*)Qb + (((size_t)amt * 4 + c) << 14),
                                  16384, m_full);
                    CP_ASYNC_BULK(st + 16384,
                                  (const char*)Kb + (((size_t)bmt0 * 4 + c) << 14),
                                  16384, m_full);
                    CP_ASYNC_BULK(st + 32768,
                                  (const char*)Kb + (((size_t)(bmt0 + 1) * 4 + c) << 14),
                                  16384, m_full);
                }
            }
        }
    } else if (wid == 0) {
        // -------- consumer (MMA) --------
        if (elect_one_pred()) {
            int g = 0, i = 0;
            for (int t = blockIdx.x; t < NTILES; t += SC_GRID, i++) {
                const int d = i & 1;
                if (i >= 2) {
                    const int u = (i - 2) >> 1;
                    MBARRIER_WAIT_PARITY(sb + 80 + d * 8, u & 1);
                }
                for (int c = 0; c < 4; c++, g++) {
                    const int s = g & 3;
                    const int u = g >> 2;
                    const uint32_t m_full = sb + s * 8;
                    const uint32_t m_emp  = sb + 32 + s * 8;
                    MBARRIER_WAIT_PARITY(m_full, u & 1);
#pragma unroll
                    for (int k = 0; k < 4; k++)
                        TCGEN05_MMA_F16_SS(tmem + d * 256,
                                           dA[s] + k * 2, dB[s] + k * 2,
                                           IDESC_F16_128x256,
                                           (c > 0) || (k > 0));
                    TCGEN05_COMMIT(m_emp);
                }
                TCGEN05_COMMIT(sb + 64 + d * 8);   // mma_done[d]
            }
        }
    } else if (wid >= 2 && wid < 6) {
        // -------- epilogue (warps 2-5; subpartition = wid & 3) --------
        const int qrow = (wid & 3) * 32 + lane;
        int i = 0;
        for (int t = blockIdx.x; t < NTILES; t += SC_GRID, i++) {
            const int d = i & 1;
            const int u = i >> 1;
            MBARRIER_WAIT_PARITY(sb + 64 + d * 8, u & 1);
            TCGEN05_FENCE_AFTER();

            const int bz = t >> 7;
            const int my = (t & 127) >> 3;
            const int nx = t & 7;
            const int m = my * 128 + qrow;
            __nv_bfloat16* crow = E + (size_t)bz * kS * kS + (size_t)m * kS
                                  + nx * 256;
            const float* mfp = maskf + (size_t)bz * kS + nx * 256;
            const uint32_t tbase = tmem + d * 256;
            float rs = 0.0f;
#pragma unroll
            for (int gg = 0; gg < 8; gg++) {
                const int col0 = gg * 32;
                float mf[32];
#pragma unroll
                for (int j = 0; j < 8; j++)
                    *(float4*)&mf[j * 4] = *(const float4*)&mfp[col0 + j * 4];
                uint32_t r[32];
                TCGEN05_LD_32X32B_X32(r, tbase + col0);
                TCGEN05_WAIT_LD();
                float e[32];
#pragma unroll
                for (int j = 0; j < 32; j++) {
                    e[j] = __expf(__uint_as_float(r[j]) * scale) * mf[j];
                    rs += e[j];
                }
                uint32_t pk[16];
#pragma unroll
                for (int j = 0; j < 16; j++)
                    pk[j] = pack_bf16x2(e[j * 2], e[j * 2 + 1]);
#pragma unroll
                for (int j = 0; j < 4; j++)
                    *(uint4*)&crow[col0 + j * 8] = *(uint4*)&pk[j * 4];
            }
            rpart[((size_t)nx * kB + bz) * kS + m] = rs;
            TCGEN05_FENCE_BEFORE();
            MBARRIER_ARRIVE(sb + 80 + d * 8);      // epi_done[d]
        }
    }

    __syncthreads();
    if (wid == 0) TCGEN05_DEALLOC(tmem, 512);

#else
    // SIMT fallback — loops over tiles, reads fp16 blocked Q/K.
    constexpr int BK = 16, TM = 8, TN = 8;
    float* As = (float*)smem;
    float* Bs = As + BK * 128;
    const int tx = tid & 15, ty = tid >> 4;

    for (int t = blockIdx.x; t < NTILES; t += SC_GRID) {
        const int bz = t >> 7;
        const int my = (t & 127) >> 3;
        const int nx = t & 7;
        const int amt  = bz * 16 + my;
        const int bmt0 = bz * 16 + nx * 2;
        const int bm = my * 128;
        const int bn = nx * 256;
        __nv_bfloat16* C = E + (size_t)bz * kS * kS;
        const float* mfp = maskf + (size_t)bz * kS;

        float rs[TM];
#pragma unroll
        for (int i = 0; i < TM; i++) rs[i] = 0.0f;

        for (int nh = 0; nh < 2; nh++) {
            const int bmtl = bmt0 + nh;
            float acc[TM][TN];
#pragma unroll
            for (int i = 0; i < TM; i++)
#pragma unroll
                for (int j = 0; j < TN; j++) acc[i][j] = 0.0f;

            for (int k0 = 0; k0 < kD; k0 += BK) {
                __syncthreads();
                for (int li = tid; li < 128 * BK; li += 256) {
                    int row = li / BK, kc = li % BK;
                    As[kc * 128 + row] = __half2float(*(const __half*)
                        ((const char*)Qb + qk16_byte_off(amt, k0 + kc, row)));
                    Bs[kc * 128 + row] = __half2float(*(const __half*)
                        ((const char*)Kb + qk16_byte_off(bmtl, k0 + kc, row)));
                }
                __syncthreads();
#pragma unroll
                for (int kk = 0; kk < BK; kk++) {
                    float a[TM], bb[TN];
                    *(float4*)&a[0]  = *(const float4*)&As[kk * 128 + ty * TM];
                    *(float4*)&a[4]  = *(const float4*)&As[kk * 128 + ty * TM + 4];
                    *(float4*)&bb[0] = *(const float4*)&Bs[kk * 128 + tx * TN];
                    *(float4*)&bb[4] = *(const float4*)&Bs[kk * 128 + tx * TN + 4];
#pragma unroll
                    for (int i = 0; i < TM; i++)
#pragma unroll
                        for (int j = 0; j < TN; j++)
                            acc[i][j] = fmaf(a[i], bb[j], acc[i][j]);
                }
            }
            const int row0 = bm + ty * TM;
            const int col0 = bn + nh * 128 + tx * TN;
#pragma unroll
            for (int i = 0; i < TM; i++)
#pragma unroll
                for (int j = 0; j < TN; j++) {
                    float e = __expf(acc[i][j] * scale) * mfp[col0 + j];
                    C[(size_t)(row0 + i) * kS + col0 + j] = __float2bfloat16(e);
                    rs[i] += e;
                }
            __syncthreads();
        }
#pragma unroll
        for (int i = 0; i < TM; i++) {
            float v = rs[i];
#pragma unroll
            for (int o = 8; o; o >>= 1) v += __shfl_xor_sync(0xffffffffu, v, o);
            if (tx == 0)
                rpart[((size_t)nx * kB + bz) * kS + bm + ty * TM + i] = v;
        }
        __syncthreads();
    }
#endif
}

// ---------------------------------------------------------------------------
// Column-sum stream over bf16 E with inline invr (from rpart partials).
// ---------------------------------------------------------------------------
__global__ __launch_bounds__(256)
void colsum_stream_kernel(const __nv_bfloat16* __restrict__ E,
                          const float* __restrict__ rpart,
                          float* __restrict__ wpart)
{
    __shared__ float s_inv[32];
    const int ch = blockIdx.x;
    const int b  = blockIdx.y;
    const int tid = threadIdx.x;

    if (tid < 32) {
        const size_t q = (size_t)b * kS + (size_t)ch * 32 + tid;
        float s = 0.0f;
#pragma unroll
        for (int c = 0; c < NXT; c++) s += rpart[(size_t)c * (kB * kS) + q];
        s_inv[tid] = 1.0f / s;
    }
    __syncthreads();

    const __nv_bfloat16* base = E + ((size_t)b * kS + (size_t)ch * 32) * kS;
    float wacc[8];
#pragma unroll
    for (int i = 0; i < 8; i++) wacc[i] = 0.0f;

    for (int r = 0; r < 32; r++) {
        const float s = s_inv[r];
        const __nv_bfloat16* p = base + (size_t)r * kS + tid * 8;
        uint4 v = *(const uint4*)p;
        const uint32_t pk[4] = {v.x, v.y, v.z, v.w};
#pragma unroll
        for (int i = 0; i < 4; i++) {
            float2 f = __bfloat1622float2(*(const __nv_bfloat162*)&pk[i]);
            wacc[i * 2]     = fmaf(f.x, s, wacc[i * 2]);
            wacc[i * 2 + 1] = fmaf(f.y, s, wacc[i * 2 + 1]);
        }
    }

    float* o = wpart + (size_t)ch * (kB * kS) + (size_t)b * kS + tid * 8;
    *(float4*)&o[0] = make_float4(wacc[0], wacc[1], wacc[2], wacc[3]);
    *(float4*)&o[4] = make_float4(wacc[4], wacc[5], wacc[6], wacc[7]);
}

// ---------------------------------------------------------------------------
// out_part: w segment reduced from wpart in-block, then o = sum_k w_k V[k,d].
// ---------------------------------------------------------------------------
__global__ __launch_bounds__(256)
void out_part_kernel(const float* __restrict__ wpart, const __half* __restrict__ V,
                     float* __restrict__ opart)
{
    __shared__ float ws[64];
    const int chunk = blockIdx.x;
    const int b     = blockIdx.y;
    const int tid   = threadIdx.x;

    if (tid < 64) {
        const int key = chunk * 64 + tid;
        float s = 0.0f;
#pragma unroll 8
        for (int c = 0; c < QCH; c++)
            s += wpart[(size_t)c * (kB * kS) + (size_t)b * kS + key];
        ws[tid] = s;
    }
    __syncthreads();

    const __half* vb = V + ((size_t)b * kS + (size_t)chunk * 64) * kD;
    float s = 0.0f;
#pragma unroll
    for (int k = 0; k < 64; k++)
        s = fmaf(ws[k], __half2float(vb[(size_t)k * kD + tid]), s);
    opart[(size_t)(chunk * kB + b) * kD + tid] = s;
}

__global__ __launch_bounds__(256)
void out_reduce_kernel(const float* __restrict__ opart, float* __restrict__ out)
{
    const int i = blockIdx.x * 256 + threadIdx.x;
    float s = 0.0f;
#pragma unroll
    for (int c = 0; c < N_KCHUNK; c++) s += opart[(size_t)c * (kB * kD) + i];
    out[i] = s * (1.0f / (float)kS);
}

// ---------------------------------------------------------------------------
// Launch
// ---------------------------------------------------------------------------
extern "C" void kernel_launch(void* const* d_in, const int* in_sizes, int n_in,
                              void* d_out, int out_size)
{
    const float* nodes = (const float*)d_in[0];
    const int*   mask  = (const int*)  d_in[1];
    const float* Wq    = (const float*)d_in[2];
    const float* bq    = (const float*)d_in[3];
    const float* Wk    = (const float*)d_in[4];
    const float* bk    = (const float*)d_in[5];
    const float* Wv    = (const float*)d_in[6];
    const float* bv    = (const float*)d_in[7];
    float* out = (float*)d_out;

    float *maskf, *rpart, *wpart, *opart;
    __half *Nb, *Wh, *Wl, *Qb, *Kb, *V;
    __nv_bfloat16* E;
    cudaGetSymbolAddress((void**)&Nb,    g_Nb);
    cudaGetSymbolAddress((void**)&Wh,    g_Wh);
    cudaGetSymbolAddress((void**)&Wl,    g_Wl);
    cudaGetSymbolAddress((void**)&Qb,    g_Qb);
    cudaGetSymbolAddress((void**)&Kb,    g_Kb);
    cudaGetSymbolAddress((void**)&V,     g_V);
    cudaGetSymbolAddress((void**)&maskf, g_maskf);
    cudaGetSymbolAddress((void**)&E,     g_E);
    cudaGetSymbolAddress((void**)&rpart, g_rpart);
    cudaGetSymbolAddress((void**)&wpart, g_wpart);
    cudaGetSymbolAddress((void**)&opart, g_opart);

    cudaFuncSetAttribute(proj_gemm,
                         cudaFuncAttributeMaxDynamicSharedMemorySize, PJ_SMEM);
    cudaFuncSetAttribute(score_gemm,
                         cudaFuncAttributeMaxDynamicSharedMemorySize, SC_SMEM);

    dim3 blk(256);

    // 0. Prep: nodes -> fp16 blocked; weights -> fp16 hi/lo; mask -> floats.
    nodes_prep<<<dim3(4, kM / 128), blk>>>(nodes, Nb);
    wsplit_prep<<<dim3(4, 2, 3), blk>>>(Wq, Wk, Wv, Wh, Wl);
    maskf_prep<<<kB, blk>>>(mask, maskf);

    // 1. Projections (fp16 MMA): grid (2 nx, 128 my, 3 w), 2 CTAs/SM.
    dim3 gproj(2, kM / 128, 3);
    proj_gemm<<<gproj, blk, PJ_SMEM>>>(Nb, Wh, Wl, bq, bk, bv, Qb, Kb, V);

    // 2. Scores: persistent warp-specialized kernel, 148 CTAs.
    score_gemm<<<SC_GRID, blk, SC_SMEM>>>(Qb, Kb, maskf, E, rpart, 0.0625f);

    // 3. colsum (inline invr), w-reduce + output contraction over fp16 V.
    colsum_stream_kernel<<<dim3(QCH, kB), blk>>>(E, rpart, wpart);
    out_part_kernel<<<dim3(N_KCHUNK, kB), blk>>>(wpart, V, opart);
    out_reduce_kernel<<<(kB * kD) / 256, blk>>>(opart, out);
}

// round 17
// speedup vs baseline: 1.5779x; 1.0521x over previous
#include <cuda_runtime.h>
#include <cuda_bf16.h>
#include <cuda_fp16.h>
#include <cstdint>
#include <math.h>

// ---------------------------------------------------------------------------
// Problem constants
// ---------------------------------------------------------------------------
static constexpr int kB = 8;
static constexpr int kS = 2048;
static constexpr int kD = 256;
static constexpr int kM = kB * kS;
static constexpr int QCH = 64;       // colsum: 32 rows per chunk
static constexpr int N_KCHUNK = 32;  // output split over keys
static constexpr int NXT = kS / 256; // 8 n-tiles per batch row
static constexpr int NTILES = kB * (kS / 128) * (kS / 256);  // 1024

// Scratch (static device memory)
// fp16 blocked layout: block = [128 rows x 64 cols] = 16KB, SW128-swizzled.
__device__ __half g_Nb[kM * kD];                       // fp16 nodes, blocked
__device__ __half g_Wh[3 * kD * kD];                   // weight hi fp16 (q,k,v)
__device__ __half g_Wl[2 * kD * kD];                   // weight lo fp16 (q,k)
__device__ __half g_Qb[kB * kS * kD];                  // fp16 q, blocked
__device__ __half g_Kb[kB * kS * kD];                  // fp16 k, blocked
__device__ __half g_V[kB * kS * kD];                   // fp16 v, row-major
__device__ float  g_maskf[kB * kS];                    // 1.0 / 0.0 mask factors
__device__ __nv_bfloat16 g_E[(size_t)kB * kS * kS];    // exp scores (bf16)
__device__ float g_rpart[NXT * kB * kS];
__device__ float g_wpart[QCH * kB * kS];
__device__ float g_opart[N_KCHUNK * kB * kD];

#if defined(__CUDA_ARCH__) && defined(__CUDA_ARCH_FEAT_SM103_ALL)
#define HAS_TCGEN05 1
#else
#define HAS_TCGEN05 0
#endif

#define SMEM_SWIZZLE_128B(byte_offset) \
    ((byte_offset) ^ (((byte_offset) >> 3) & 0x70))

__device__ __forceinline__ uint32_t smem_to_u32_gen(const void* p) {
    uint32_t a;
    asm("{ .reg .u64 t; cvta.to.shared.u64 t, %1; cvt.u32.u64 %0, t; }"
        : "=r"(a) : "l"(p));
    return a;
}

__device__ __forceinline__ uint32_t pack_bf16x2(float lo, float hi) {
    uint32_t r;
    asm("cvt.rn.bf16x2.f32 %0, %1, %2;" : "=r"(r) : "f"(hi), "f"(lo));
    return r;
}

__device__ __forceinline__ uint32_t pack_f16x2(float lo, float hi) {
    uint32_t r;
    asm("cvt.rn.f16x2.f32 %0, %1, %2;" : "=r"(r) : "f"(hi), "f"(lo));
    return r;
}

// fp16 blocked: BYTE offset of element (col in [0,256), row r in [0,128))
__device__ __forceinline__ size_t qk16_byte_off(int gmtile, int col, int r) {
    uint32_t base = (uint32_t)(r * 128 + ((col & 63) >> 3) * 16);
    uint32_t sw = SMEM_SWIZZLE_128B(base) + (uint32_t)(col & 7) * 2;
    return ((size_t)(gmtile * 4 + (col >> 6)) << 14) + sw;
}

#if HAS_TCGEN05
__device__ __forceinline__ uint32_t elect_one_pred() {
    uint32_t pred;
    asm volatile(
        "{\n\t.reg .pred p;\n\t"
        "elect.sync _|p, 0xFFFFFFFF;\n\t"
        "selp.b32 %0, 1, 0, p;\n\t}"
        : "=r"(pred));
    return pred;
}

#define TCGEN05_ALLOC(smem_result_addr, nCols) \
    asm volatile("tcgen05.alloc.cta_group::1.sync.aligned.shared::cta.b32 [%0], %1;" \
                 :: "r"((uint32_t)(smem_result_addr)), "r"((uint32_t)(nCols)) : "memory")
#define TCGEN05_DEALLOC(tmem_addr, nCols) \
    asm volatile("tcgen05.dealloc.cta_group::1.sync.aligned.b32 %0, %1;" \
                 :: "r"(tmem_addr), "r"((uint32_t)(nCols)))
#define TCGEN05_RELINQUISH() \
    asm volatile("tcgen05.relinquish_alloc_permit.cta_group::1.sync.aligned;")
#define TCGEN05_COMMIT(mbar_smem_addr) \
    asm volatile("tcgen05.commit.cta_group::1.mbarrier::arrive::one.shared::cluster.b64 [%0];" \
                 :: "r"((uint32_t)(mbar_smem_addr)) : "memory")
#define TCGEN05_FENCE_AFTER() \
    asm volatile("tcgen05.fence::after_thread_sync;" ::: "memory")
#define TCGEN05_FENCE_BEFORE() \
    asm volatile("tcgen05.fence::before_thread_sync;" ::: "memory")
#define TCGEN05_WAIT_LD() \
    asm volatile("tcgen05.wait::ld.sync.aligned;" ::: "memory")
#define MBARRIER_INIT(mbar_smem_addr, count) \
    asm volatile("mbarrier.init.shared.b64 [%0], %1;" \
                 :: "r"((uint32_t)(mbar_smem_addr)), "r"((uint32_t)(count)) : "memory")
#define MBARRIER_ARRIVE(mbar_smem_addr) \
    asm volatile("mbarrier.arrive.shared.b64 _, [%0];" \
                 :: "r"((uint32_t)(mbar_smem_addr)) : "memory")
#define MBARRIER_EXPECT_TX(mbar_smem_addr, tx_bytes) \
    asm volatile("mbarrier.arrive.expect_tx.shared.b64 _, [%0], %1;" \
                 :: "r"((uint32_t)(mbar_smem_addr)), "r"((uint32_t)(tx_bytes)) : "memory")
#define NAMED_BARRIER_SYNC(barrier_id, thread_count) \
    asm volatile("bar.sync %0, %1;" :: "r"(barrier_id), "r"(thread_count) : "memory")

#define MBARRIER_WAIT_PARITY(mbar_smem_addr, phase_parity) do { \
    uint32_t _mbar = (uint32_t)(mbar_smem_addr); \
    uint32_t _parity = (uint32_t)(phase_parity); \
    uint32_t _done; \
    asm volatile( \
        "{\n\t.reg .pred p;\n\t" \
        "mbarrier.try_wait.parity.acquire.cta.shared::cta.b64 p, [%1], %2;\n\t" \
        "selp.b32 %0, 1, 0, p;\n\t}" \
        : "=r"(_done) : "r"(_mbar), "r"(_parity) : "memory"); \
    if (!_done) { \
        asm volatile( \
            "{\n\t.reg .pred P1;\n\t" \
            "WAIT_LOOP_%=:\n\t" \
            "mbarrier.try_wait.parity.acquire.cta.shared::cta.b64 P1, [%0], %1, 0x989680;\n\t" \
            "@P1 bra.uni WAIT_DONE_%=;\n\t" \
            "bra.uni WAIT_LOOP_%=;\n\t" \
            "WAIT_DONE_%=:\n\t}" \
            :: "r"(_mbar), "r"(_parity) : "memory"); \
    } \
} while(0)

#define TCGEN05_LD_32X32B_X32(r, tmem_addr) \
    asm volatile( \
        "tcgen05.ld.sync.aligned.32x32b.x32.b32 " \
        "{%0, %1, %2, %3, %4, %5, %6, %7, " \
        " %8, %9, %10, %11, %12, %13, %14, %15, " \
        " %16, %17, %18, %19, %20, %21, %22, %23, " \
        " %24, %25, %26, %27, %28, %29, %30, %31}, [%32];" \
        : "=r"((r)[0]),  "=r"((r)[1]),  "=r"((r)[2]),  "=r"((r)[3]), \
          "=r"((r)[4]),  "=r"((r)[5]),  "=r"((r)[6]),  "=r"((r)[7]), \
          "=r"((r)[8]),  "=r"((r)[9]),  "=r"((r)[10]), "=r"((r)[11]), \
          "=r"((r)[12]), "=r"((r)[13]), "=r"((r)[14]), "=r"((r)[15]), \
          "=r"((r)[16]), "=r"((r)[17]), "=r"((r)[18]), "=r"((r)[19]), \
          "=r"((r)[20]), "=r"((r)[21]), "=r"((r)[22]), "=r"((r)[23]), \
          "=r"((r)[24]), "=r"((r)[25]), "=r"((r)[26]), "=r"((r)[27]), \
          "=r"((r)[28]), "=r"((r)[29]), "=r"((r)[30]), "=r"((r)[31]) \
        : "r"(tmem_addr))

#define TCGEN05_MMA_F16_SS(d_tmem, a_desc, b_desc, idesc, enable_d) do { \
    uint32_t _en = (enable_d) ? 1u : 0u; \
    uint32_t _zero = 0u; \
    asm volatile( \
        "{\n\t.reg .pred p;\n\t" \
        "setp.ne.u32 p, %5, 0;\n\t" \
        "tcgen05.mma.cta_group::1.kind::f16 [%0], %1, %2, %3, {%4, %4, %4, %4}, p;\n\t" \
        "}" \
        :: "r"(d_tmem), "l"(a_desc), "l"(b_desc), "r"(idesc), "r"(_zero), "r"(_en) \
        : "memory"); \
} while(0)

static constexpr uint64_t SMEM_DESC_BASE_SW128 =
    (uint64_t(2)  << 61) | (uint64_t(1) << 46) | (uint64_t(64) << 32) | (uint64_t(1) << 16);
#define MAKE_SMEM_DESC(base_addr) \
    (SMEM_DESC_BASE_SW128 | ((uint64_t)((base_addr) >> 4) & 0x3FFF))

#define CP_ASYNC_BULK(dst_smem, src_gmem, bytes, mbar) \
    asm volatile("cp.async.bulk.shared::cta.global.mbarrier::complete_tx::bytes " \
                 "[%0], [%1], %2, [%3];" \
                 :: "r"((uint32_t)(dst_smem)), "l"(src_gmem), \
                    "r"((uint32_t)(bytes)), "r"((uint32_t)(mbar)) : "memory")

// IDESCs (F32 accum, fp16 operands)
static constexpr uint32_t IDESC_F16_128x128 =
    (1u << 4) | (0u << 7) | (0u << 10) | ((128 / 8) << 17) | ((128 / 16) << 24);
static constexpr uint32_t IDESC_F16_128x256 =
    (1u << 4) | (0u << 7) | (0u << 10) | ((256 / 8) << 17) | ((128 / 16) << 24);
#endif  // HAS_TCGEN05

// ---------------------------------------------------------------------------
// Prep 1: nodes -> fp16 blocked. grid (4 kc, kM/128).
// ---------------------------------------------------------------------------
__global__ __launch_bounds__(256)
void nodes_prep(const float* __restrict__ src, __half* __restrict__ Nb)
{
    const int kc = blockIdx.x;
    const int mt = blockIdx.y;
    const int tid = threadIdx.x;
    char* blk = (char*)(Nb + (((size_t)mt * 4 + kc) << 13));
#pragma unroll
    for (int t = 0; t < 4; t++) {
        int idx = tid + t * 256;
        int row = idx >> 3, j = idx & 7;
        const float* s = src + (size_t)(mt * 128 + row) * kD + kc * 64 + j * 8;
        float4 a = *(const float4*)s;
        float4 b = *(const float4*)(s + 4);
        uint32_t pk[4];
        pk[0] = pack_f16x2(a.x, a.y);
        pk[1] = pack_f16x2(a.z, a.w);
        pk[2] = pack_f16x2(b.x, b.y);
        pk[3] = pack_f16x2(b.z, b.w);
        uint32_t sw = SMEM_SWIZZLE_128B((uint32_t)(row * 128 + j * 16));
        *(uint4*)(blk + sw) = *(uint4*)pk;
    }
}

// ---------------------------------------------------------------------------
// Prep 2: weights -> fp16 (hi, lo) split, blocked. grid (4 kc, 2 mt, 3 w).
// ---------------------------------------------------------------------------
__global__ __launch_bounds__(256)
void wsplit_prep(const float* __restrict__ Wq, const float* __restrict__ Wk,
                 const float* __restrict__ Wv,
                 __half* __restrict__ Wh, __half* __restrict__ Wl)
{
    const int kc = blockIdx.x;
    const int mt = blockIdx.y;
    const int w  = blockIdx.z;
    const int tid = threadIdx.x;
    const float* W = (w == 0) ? Wq : (w == 1) ? Wk : Wv;
    char* bh = (char*)(Wh + (size_t)w * (kD * kD) + (((size_t)mt * 4 + kc) << 13));
    char* bl = (w < 2)
        ? (char*)(Wl + (size_t)w * (kD * kD) + (((size_t)mt * 4 + kc) << 13))
        : nullptr;
#pragma unroll
    for (int t = 0; t < 4; t++) {
        int idx = tid + t * 256;
        int row = idx >> 3, j = idx & 7;
        const float* s = W + (size_t)(mt * 128 + row) * kD + kc * 64 + j * 8;
        float x[8];
        *(float4*)&x[0] = *(const float4*)s;
        *(float4*)&x[4] = *(const float4*)(s + 4);
        float h[8], l[8];
#pragma unroll
        for (int i = 0; i < 8; i++) {
            h[i] = __half2float(__float2half_rn(x[i]));
            l[i] = x[i] - h[i];
        }
        uint32_t pkh[4], pkl[4];
#pragma unroll
        for (int i = 0; i < 4; i++) {
            pkh[i] = pack_f16x2(h[i * 2], h[i * 2 + 1]);
            pkl[i] = pack_f16x2(l[i * 2], l[i * 2 + 1]);
        }
        uint32_t sw = SMEM_SWIZZLE_128B((uint32_t)(row * 128 + j * 16));
        *(uint4*)(bh + sw) = *(uint4*)pkh;
        if (bl) *(uint4*)(bl + sw) = *(uint4*)pkl;
    }
}

// ---------------------------------------------------------------------------
// Prep 3: mask -> float factors. grid (kB).
// ---------------------------------------------------------------------------
__global__ __launch_bounds__(256)
void maskf_prep(const int* __restrict__ mask, float* __restrict__ maskf)
{
    const int b = blockIdx.x;
    const int tid = threadIdx.x;
#pragma unroll
    for (int t = 0; t < 8; t++) {
        int k = tid + t * 256;
        maskf[b * kS + k] = (mask[b * kS + k] != 0) ? 1.0f : 0.0f;
    }
}

// ---------------------------------------------------------------------------
// Pipelined fp16 projection GEMM, BM=128, BN=128, grid (2 nx, 128 my, 3 w).
// [unchanged from R15/16]
// ---------------------------------------------------------------------------
static constexpr int PJ_STAGE = 49152;
static constexpr int PJ_SMEM = 2048 + 2 * PJ_STAGE;   // 100352

__global__ __launch_bounds__(256)
void proj_gemm(const __half* __restrict__ Nb,
               const __half* __restrict__ Wh, const __half* __restrict__ Wl,
               const float* __restrict__ b0, const float* __restrict__ b1,
               const float* __restrict__ b2,
               __half* __restrict__ C0, __half* __restrict__ C1,
               __half* __restrict__ C2)
{
    extern __shared__ __align__(1024) char smem[];
    const int tid = threadIdx.x;
    const int nx = blockIdx.x;
    const int my = blockIdx.y;
    const int w  = blockIdx.z;
    const float* bias = (w == 0) ? b0 : (w == 1) ? b1 : b2;
    const bool two_pass = (w < 2);
    __half* Ch = (w == 0) ? C0 : (w == 1) ? C1 : C2;
    const char* WhB = (const char*)(Wh + (size_t)w * (kD * kD));
    const char* WlB = (const char*)(Wl + (size_t)w * (kD * kD));
    const char* NbB = (const char*)Nb;
    const int bn = nx * 128;
    const int bm = my * 128;

#if HAS_TCGEN05
    const uint32_t sb = smem_to_u32_gen(smem);
    const uint32_t m_done = sb + 32;
    float* s_bias = (float*)(smem + 1024);
    const int wid = tid >> 5;

    if (wid == 0) { TCGEN05_ALLOC(sb + 40, 128); TCGEN05_RELINQUISH(); }
    if (tid == 0) {
        MBARRIER_INIT(sb + 0, 1);
        MBARRIER_INIT(sb + 8, 1);
        MBARRIER_INIT(sb + 16, 1);
        MBARRIER_INIT(sb + 24, 1);
        MBARRIER_INIT(m_done, 1);
    }
    if (tid < 128) s_bias[tid] = bias[bn + tid];
    __syncthreads();
    const uint32_t tmem = *(volatile uint32_t*)(smem + 40);

    uint64_t dA[2], dBh[2], dBl[2];
#pragma unroll
    for (int s = 0; s < 2; s++) {
        uint32_t base = sb + 2048 + s * PJ_STAGE;
        dA[s]  = MAKE_SMEM_DESC(base);
        dBh[s] = MAKE_SMEM_DESC(base + 16384);
        dBl[s] = MAKE_SMEM_DESC(base + 32768);
    }

    const uint32_t tx_bytes = two_pass ? 49152u : 32768u;

    if (wid == 1) {
        if (elect_one_pred()) {
            for (int c = 0; c < 4; c++) {
                const int s = c & 1;
                const int i = c >> 1;
                const uint32_t m_full = sb + s * 8;
                const uint32_t m_emp  = sb + 16 + s * 8;
                const uint32_t st = sb + 2048 + s * PJ_STAGE;
                MBARRIER_WAIT_PARITY(m_emp, 1 ^ (i & 1));
                MBARRIER_EXPECT_TX(m_full, tx_bytes);
                CP_ASYNC_BULK(st,
                              NbB + (((size_t)my * 4 + c) << 14), 16384, m_full);
                CP_ASYNC_BULK(st + 16384,
                              WhB + (((size_t)nx * 4 + c) << 14), 16384, m_full);
                if (two_pass)
                    CP_ASYNC_BULK(st + 32768,
                                  WlB + (((size_t)nx * 4 + c) << 14), 16384, m_full);
            }
        }
    } else if (wid == 0) {
        if (elect_one_pred()) {
            for (int c = 0; c < 4; c++) {
                const int s = c & 1;
                const int i = c >> 1;
                const uint32_t m_full = sb + s * 8;
                const uint32_t m_emp  = sb + 16 + s * 8;
                MBARRIER_WAIT_PARITY(m_full, i & 1);
#pragma unroll
                for (int k = 0; k < 4; k++)
                    TCGEN05_MMA_F16_SS(tmem, dA[s] + k * 2, dBh[s] + k * 2,
                                       IDESC_F16_128x128, (c > 0) || (k > 0));
                if (two_pass) {
#pragma unroll
                    for (int k = 0; k < 4; k++)
                        TCGEN05_MMA_F16_SS(tmem, dA[s] + k * 2, dBl[s] + k * 2,
                                           IDESC_F16_128x128, true);
                }
                TCGEN05_COMMIT(m_emp);
            }
            TCGEN05_COMMIT(m_done);
        }
    }

    MBARRIER_WAIT_PARITY(m_done, 0);
    TCGEN05_FENCE_AFTER();

    {
        const int lane = tid & 31;
        const int half = wid >> 2;
        const int mloc = (wid & 3) * 32 + lane;
        const int m = bm + mloc;
#pragma unroll
        for (int g = 0; g < 2; g++) {
            const int col0 = half * 64 + g * 32;
            uint32_t r[32];
            TCGEN05_LD_32X32B_X32(r, tmem + col0);
            TCGEN05_WAIT_LD();
            float e[32];
#pragma unroll
            for (int j = 0; j < 32; j++)
                e[j] = __uint_as_float(r[j]) + s_bias[col0 + j];
            uint32_t pk[16];
#pragma unroll
            for (int j = 0; j < 16; j++)
                pk[j] = pack_f16x2(e[j * 2], e[j * 2 + 1]);
            if (two_pass) {
                __half* blk = Ch + (((size_t)(m >> 7) * 4 + nx * 2 + half) << 13);
#pragma unroll
                for (int j = 0; j < 4; j++) {
                    uint32_t sw = SMEM_SWIZZLE_128B(
                        (uint32_t)(mloc * 128 + g * 64 + j * 16));
                    *(uint4*)((char*)blk + sw) = *(uint4*)&pk[j * 4];
                }
            } else {
                __half* crow = Ch + (size_t)m * kD + bn + col0;
#pragma unroll
                for (int j = 0; j < 4; j++)
                    *(uint4*)&crow[j * 8] = *(uint4*)&pk[j * 4];
            }
        }
    }
    __syncthreads();
    if (wid == 0) TCGEN05_DEALLOC(tmem, 128);

#else
    // SIMT fallback — reads fp16 blocked Nb / Wh / Wl.
    constexpr int BK = 16, TM = 8, TN = 8;
    float* As = (float*)smem;
    float* Bs = As + BK * 128;
    const int tx = tid & 15, ty = tid >> 4;

    float acc[TM][TN];
#pragma unroll
    for (int i = 0; i < TM; i++)
#pragma unroll
        for (int j = 0; j < TN; j++) acc[i][j] = 0.0f;

    for (int k0 = 0; k0 < kD; k0 += BK) {
        __syncthreads();
        for (int li = tid; li < 128 * BK; li += 256) {
            int row = li / BK, kc = li % BK;
            size_t offA = qk16_byte_off(my, k0 + kc, row);
            size_t offB = qk16_byte_off(nx, k0 + kc, row);
            As[kc * 128 + row] = __half2float(*(const __half*)(NbB + offA));
            float bw = __half2float(*(const __half*)(WhB + offB));
            if (two_pass) bw += __half2float(*(const __half*)(WlB + offB));
            Bs[kc * 128 + row] = bw;
        }
        __syncthreads();
#pragma unroll
        for (int kk = 0; kk < BK; kk++) {
            float a[TM], bb[TN];
            *(float4*)&a[0]  = *(const float4*)&As[kk * 128 + ty * TM];
            *(float4*)&a[4]  = *(const float4*)&As[kk * 128 + ty * TM + 4];
            *(float4*)&bb[0] = *(const float4*)&Bs[kk * 128 + tx * TN];
            *(float4*)&bb[4] = *(const float4*)&Bs[kk * 128 + tx * TN + 4];
#pragma unroll
            for (int i = 0; i < TM; i++)
#pragma unroll
                for (int j = 0; j < TN; j++)
                    acc[i][j] = fmaf(a[i], bb[j], acc[i][j]);
        }
    }
    const int row0 = bm + ty * TM, col0 = bn + tx * TN;
#pragma unroll
    for (int i = 0; i < TM; i++)
#pragma unroll
        for (int j = 0; j < TN; j++) {
            float v = acc[i][j] + bias[col0 + j];
            int m = row0 + i, n = col0 + j;
            if (two_pass)
                *(__half*)((char*)Ch + qk16_byte_off(m >> 7, n, m & 127)) =
                    __float2half_rn(v);
            else
                Ch[(size_t)m * kD + n] = __float2half_rn(v);
        }
#endif
}

// ---------------------------------------------------------------------------
// PERSISTENT scores kernel, 320 threads: grid 148 CTAs, ~7 tiles each.
// Warp roles: w8 = producer (bulk loads, 4-stage ring);
//             w9 = MMA consumer (TMEM double buffer D0/D1);
//             w0-7 = epilogue: group (wid>>2) takes cols 0-127 / 128-255,
//                    subpartition = wid & 3 (all 4 covered per group).
// smem ctrl: full[4]@0..24, empty[4]@32..56, mma_done[2]@64,72,
//            epi_done[2]@80,88 (count 256), tmem@96, rs2[2][128]@256.
// stages: 4 x 48KB {Q 16K | K 32K}; total 198656 smem.
// ---------------------------------------------------------------------------
static constexpr int SC_STAGE = 49152;
static constexpr int SC_SMEM = 2048 + 4 * SC_STAGE;   // 198656
static constexpr int SC_GRID = 148;
static constexpr int SC_THREADS = 320;

__global__ __launch_bounds__(SC_THREADS)
void score_gemm(const __half* __restrict__ Qb, const __half* __restrict__ Kb,
                const float* __restrict__ maskf, __nv_bfloat16* __restrict__ E,
                float* __restrict__ rpart, float scale)
{
    extern __shared__ __align__(1024) char smem[];
    const int tid = threadIdx.x;

#if HAS_TCGEN05
    const uint32_t sb = smem_to_u32_gen(smem);
    const int wid = tid >> 5;
    const int lane = tid & 31;
    float* s_rs2 = (float*)(smem + 256);   // [2][128]

    if (wid == 0) { TCGEN05_ALLOC(sb + 96, 512); TCGEN05_RELINQUISH(); }
    if (tid == 0) {
#pragma unroll
        for (int s = 0; s < 4; s++) {
            MBARRIER_INIT(sb + s * 8, 1);        // full[s]
            MBARRIER_INIT(sb + 32 + s * 8, 1);   // empty[s]
        }
        MBARRIER_INIT(sb + 64, 1);               // mma_done[0]
        MBARRIER_INIT(sb + 72, 1);               // mma_done[1]
        MBARRIER_INIT(sb + 80, 256);             // epi_done[0]
        MBARRIER_INIT(sb + 88, 256);             // epi_done[1]
    }
    __syncthreads();
    const uint32_t tmem = *(volatile uint32_t*)(smem + 96);

    uint64_t dA[4], dB[4];
#pragma unroll
    for (int s = 0; s < 4; s++) {
        uint32_t base = sb + 2048 + s * SC_STAGE;
        dA[s] = MAKE_SMEM_DESC(base);
        dB[s] = MAKE_SMEM_DESC(base + 16384);
    }

    if (wid == 8) {
        // -------- producer --------
        if (elect_one_pred()) {
            int g = 0;
            for (int t = blockIdx.x; t < NTILES; t += SC_GRID) {
                const int bz = t >> 7;
                const int my = (t & 127) >> 3;
                const int nx = t & 7;
                const int amt  = bz * 16 + my;
                const int bmt0 = bz * 16 + nx * 2;
                for (int c = 0; c < 4; c++, g++) {
                    const int s = g & 3;
                    const int u = g >> 2;
                    const uint32_t m_full = sb + s * 8;
                    const uint32_t m_emp  = sb + 32 + s * 8;
                    const uint32_t st = sb + 2048 + s * SC_STAGE;
                    MBARRIER_WAIT_PARITY(m_emp, 1 ^ (u & 1));
                    MBARRIER_EXPECT_TX(m_full, SC_STAGE);
                    CP_ASYNC_BULK(st,
                                  (const char*)Qb + (((size_t)amt * 4 + c) << 14),
                                  16384, m_full);
                    CP_ASYNC_BULK(st + 16384,
                                  (const char*)Kb + (((size_t)bmt0 * 4 + c) << 14),
                                  16384, m_full);
                    CP_ASYNC_BULK(st + 32768,
                                  (const char*)Kb + (((size_t)(bmt0 + 1) * 4 + c) << 14),
                                  16384, m_full);
                }
            }
        }
    } else if (wid == 9) {
        // -------- consumer (MMA) --------
        if (elect_one_pred()) {
            int g = 0, i = 0;
            for (int t = blockIdx.x; t < NTILES; t += SC_GRID, i++) {
                const int d = i & 1;
                if (i >= 2) {
                    const int u = (i - 2) >> 1;
                    MBARRIER_WAIT_PARITY(sb + 80 + d * 8, u & 1);
                }
                for (int c = 0; c < 4; c++, g++) {
                    const int s = g & 3;
                    const int u = g >> 2;
                    const uint32_t m_full = sb + s * 8;
                    const uint32_t m_emp  = sb + 32 + s * 8;
                    MBARRIER_WAIT_PARITY(m_full, u & 1);
#pragma unroll
                    for (int k = 0; k < 4; k++)
                        TCGEN05_MMA_F16_SS(tmem + d * 256,
                                           dA[s] + k * 2, dB[s] + k * 2,
                                           IDESC_F16_128x256,
                                           (c > 0) || (k > 0));
                    TCGEN05_COMMIT(m_emp);
                }
                TCGEN05_COMMIT(sb + 64 + d * 8);   // mma_done[d]
            }
        }
    } else {
        // -------- epilogue (warps 0-7) --------
        const int grp  = wid >> 2;               // 0: cols 0-127, 1: 128-255
        const int qrow = (wid & 3) * 32 + lane;  // subpartition row
        int i = 0;
        for (int t = blockIdx.x; t < NTILES; t += SC_GRID, i++) {
            const int d = i & 1;
            const int u = i >> 1;
            MBARRIER_WAIT_PARITY(sb + 64 + d * 8, u & 1);
            TCGEN05_FENCE_AFTER();

            const int bz = t >> 7;
            const int my = (t & 127) >> 3;
            const int nx = t & 7;
            const int m = my * 128 + qrow;
            __nv_bfloat16* crow = E + (size_t)bz * kS * kS + (size_t)m * kS
                                  + nx * 256 + grp * 128;
            const float* mfp = maskf + (size_t)bz * kS + nx * 256 + grp * 128;
            const uint32_t tbase = tmem + d * 256 + grp * 128;
            float rs = 0.0f;
#pragma unroll
            for (int gg = 0; gg < 4; gg++) {
                const int col0 = gg * 32;
                float mf[32];
#pragma unroll
                for (int j = 0; j < 8; j++)
                    *(float4*)&mf[j * 4] = *(const float4*)&mfp[col0 + j * 4];
                uint32_t r[32];
                TCGEN05_LD_32X32B_X32(r, tbase + col0);
                TCGEN05_WAIT_LD();
                float e[32];
#pragma unroll
                for (int j = 0; j < 32; j++) {
                    e[j] = __expf(__uint_as_float(r[j]) * scale) * mf[j];
                    rs += e[j];
                }
                uint32_t pk[16];
#pragma unroll
                for (int j = 0; j < 16; j++)
                    pk[j] = pack_bf16x2(e[j * 2], e[j * 2 + 1]);
#pragma unroll
                for (int j = 0; j < 4; j++)
                    *(uint4*)&crow[col0 + j * 8] = *(uint4*)&pk[j * 4];
            }
            // rowsum: group 1 stashes, group 0 combines and writes
            if (grp == 1) s_rs2[d * 128 + qrow] = rs;
            NAMED_BARRIER_SYNC(1, 256);
            if (grp == 0)
                rpart[((size_t)nx * kB + bz) * kS + m] = rs + s_rs2[d * 128 + qrow];
            TCGEN05_FENCE_BEFORE();
            MBARRIER_ARRIVE(sb + 80 + d * 8);      // epi_done[d]
        }
    }

    __syncthreads();
    if (wid == 0) TCGEN05_DEALLOC(tmem, 512);

#else
    // SIMT fallback — loops over tiles, reads fp16 blocked Q/K. 320 threads
    // (threads >= 256 idle in compute, help with loads).
    constexpr int BK = 16, TM = 8, TN = 8;
    float* As = (float*)smem;
    float* Bs = As + BK * 128;
    const int tx = tid & 15, ty = tid >> 4;
    const bool active = (tid < 256);

    for (int t = blockIdx.x; t < NTILES; t += SC_GRID) {
        const int bz = t >> 7;
        const int my = (t & 127) >> 3;
        const int nx = t & 7;
        const int amt  = bz * 16 + my;
        const int bmt0 = bz * 16 + nx * 2;
        const int bm = my * 128;
        const int bn = nx * 256;
        __nv_bfloat16* C = E + (size_t)bz * kS * kS;
        const float* mfp = maskf + (size_t)bz * kS;

        float rs[TM];
#pragma unroll
        for (int i = 0; i < TM; i++) rs[i] = 0.0f;

        for (int nh = 0; nh < 2; nh++) {
            const int bmtl = bmt0 + nh;
            float acc[TM][TN];
#pragma unroll
            for (int i = 0; i < TM; i++)
#pragma unroll
                for (int j = 0; j < TN; j++) acc[i][j] = 0.0f;

            for (int k0 = 0; k0 < kD; k0 += BK) {
                __syncthreads();
                for (int li = tid; li < 128 * BK; li += SC_THREADS) {
                    int row = li / BK, kc = li % BK;
                    As[kc * 128 + row] = __half2float(*(const __half*)
                        ((const char*)Qb + qk16_byte_off(amt, k0 + kc, row)));
                    Bs[kc * 128 + row] = __half2float(*(const __half*)
                        ((const char*)Kb + qk16_byte_off(bmtl, k0 + kc, row)));
                }
                __syncthreads();
                if (active) {
#pragma unroll
                    for (int kk = 0; kk < BK; kk++) {
                        float a[TM], bb[TN];
                        *(float4*)&a[0]  = *(const float4*)&As[kk * 128 + ty * TM];
                        *(float4*)&a[4]  = *(const float4*)&As[kk * 128 + ty * TM + 4];
                        *(float4*)&bb[0] = *(const float4*)&Bs[kk * 128 + tx * TN];
                        *(float4*)&bb[4] = *(const float4*)&Bs[kk * 128 + tx * TN + 4];
#pragma unroll
                        for (int i = 0; i < TM; i++)
#pragma unroll
                            for (int j = 0; j < TN; j++)
                                acc[i][j] = fmaf(a[i], bb[j], acc[i][j]);
                    }
                }
            }
            if (active) {
                const int row0 = bm + ty * TM;
                const int col0 = bn + nh * 128 + tx * TN;
#pragma unroll
                for (int i = 0; i < TM; i++)
#pragma unroll
                    for (int j = 0; j < TN; j++) {
                        float e = __expf(acc[i][j] * scale) * mfp[col0 + j];
                        C[(size_t)(row0 + i) * kS + col0 + j] = __float2bfloat16(e);
                        rs[i] += e;
                    }
            }
            __syncthreads();
        }
        if (active) {
#pragma unroll
            for (int i = 0; i < TM; i++) {
                float v = rs[i];
#pragma unroll
                for (int o = 8; o; o >>= 1) v += __shfl_xor_sync(0xffffffffu, v, o);
                if (tx == 0)
                    rpart[((size_t)nx * kB + bz) * kS + bm + ty * TM + i] = v;
            }
        }
        __syncthreads();
    }
#endif
}

// ---------------------------------------------------------------------------
// Column-sum stream over bf16 E with inline invr (from rpart partials).
// ---------------------------------------------------------------------------
__global__ __launch_bounds__(256)
void colsum_stream_kernel(const __nv_bfloat16* __restrict__ E,
                          const float* __restrict__ rpart,
                          float* __restrict__ wpart)
{
    __shared__ float s_inv[32];
    const int ch = blockIdx.x;
    const int b  = blockIdx.y;
    const int tid = threadIdx.x;

    if (tid < 32) {
        const size_t q = (size_t)b * kS + (size_t)ch * 32 + tid;
        float s = 0.0f;
#pragma unroll
        for (int c = 0; c < NXT; c++) s += rpart[(size_t)c * (kB * kS) + q];
        s_inv[tid] = 1.0f / s;
    }
    __syncthreads();

    const __nv_bfloat16* base = E + ((size_t)b * kS + (size_t)ch * 32) * kS;
    float wacc[8];
#pragma unroll
    for (int i = 0; i < 8; i++) wacc[i] = 0.0f;

    for (int r = 0; r < 32; r++) {
        const float s = s_inv[r];
        const __nv_bfloat16* p = base + (size_t)r * kS + tid * 8;
        uint4 v = *(const uint4*)p;
        const uint32_t pk[4] = {v.x, v.y, v.z, v.w};
#pragma unroll
        for (int i = 0; i < 4; i++) {
            float2 f = __bfloat1622float2(*(const __nv_bfloat162*)&pk[i]);
            wacc[i * 2]     = fmaf(f.x, s, wacc[i * 2]);
            wacc[i * 2 + 1] = fmaf(f.y, s, wacc[i * 2 + 1]);
        }
    }

    float* o = wpart + (size_t)ch * (kB * kS) + (size_t)b * kS + tid * 8;
    *(float4*)&o[0] = make_float4(wacc[0], wacc[1], wacc[2], wacc[3]);
    *(float4*)&o[4] = make_float4(wacc[4], wacc[5], wacc[6], wacc[7]);
}

// ---------------------------------------------------------------------------
// out_part: w segment reduced from wpart in-block, then o = sum_k w_k V[k,d].
// ---------------------------------------------------------------------------
__global__ __launch_bounds__(256)
void out_part_kernel(const float* __restrict__ wpart, const __half* __restrict__ V,
                     float* __restrict__ opart)
{
    __shared__ float ws[64];
    const int chunk = blockIdx.x;
    const int b     = blockIdx.y;
    const int tid   = threadIdx.x;

    if (tid < 64) {
        const int key = chunk * 64 + tid;
        float s = 0.0f;
#pragma unroll 8
        for (int c = 0; c < QCH; c++)
            s += wpart[(size_t)c * (kB * kS) + (size_t)b * kS + key];
        ws[tid] = s;
    }
    __syncthreads();

    const __half* vb = V + ((size_t)b * kS + (size_t)chunk * 64) * kD;
    float s = 0.0f;
#pragma unroll
    for (int k = 0; k < 64; k++)
        s = fmaf(ws[k], __half2float(vb[(size_t)k * kD + tid]), s);
    opart[(size_t)(chunk * kB + b) * kD + tid] = s;
}

__global__ __launch_bounds__(256)
void out_reduce_kernel(const float* __restrict__ opart, float* __restrict__ out)
{
    const int i = blockIdx.x * 256 + threadIdx.x;
    float s = 0.0f;
#pragma unroll
    for (int c = 0; c < N_KCHUNK; c++) s += opart[(size_t)c * (kB * kD) + i];
    out[i] = s * (1.0f / (float)kS);
}

// ---------------------------------------------------------------------------
// Launch
// ---------------------------------------------------------------------------
extern "C" void kernel_launch(void* const* d_in, const int* in_sizes, int n_in,
                              void* d_out, int out_size)
{
    const float* nodes = (const float*)d_in[0];
    const int*   mask  = (const int*)  d_in[1];
    const float* Wq    = (const float*)d_in[2];
    const float* bq    = (const float*)d_in[3];
    const float* Wk    = (const float*)d_in[4];
    const float* bk    = (const float*)d_in[5];
    const float* Wv    = (const float*)d_in[6];
    const float* bv    = (const float*)d_in[7];
    float* out = (float*)d_out;

    float *maskf, *rpart, *wpart, *opart;
    __half *Nb, *Wh, *Wl, *Qb, *Kb, *V;
    __nv_bfloat16* E;
    cudaGetSymbolAddress((void**)&Nb,    g_Nb);
    cudaGetSymbolAddress((void**)&Wh,    g_Wh);
    cudaGetSymbolAddress((void**)&Wl,    g_Wl);
    cudaGetSymbolAddress((void**)&Qb,    g_Qb);
    cudaGetSymbolAddress((void**)&Kb,    g_Kb);
    cudaGetSymbolAddress((void**)&V,     g_V);
    cudaGetSymbolAddress((void**)&maskf, g_maskf);
    cudaGetSymbolAddress((void**)&E,     g_E);
    cudaGetSymbolAddress((void**)&rpart, g_rpart);
    cudaGetSymbolAddress((void**)&wpart, g_wpart);
    cudaGetSymbolAddress((void**)&opart, g_opart);

    cudaFuncSetAttribute(proj_gemm,
                         cudaFuncAttributeMaxDynamicSharedMemorySize, PJ_SMEM);
    cudaFuncSetAttribute(score_gemm,
                         cudaFuncAttributeMaxDynamicSharedMemorySize, SC_SMEM);

    dim3 blk(256);

    // 0. Prep: nodes -> fp16 blocked; weights -> fp16 hi/lo; mask -> floats.
    nodes_prep<<<dim3(4, kM / 128), blk>>>(nodes, Nb);
    wsplit_prep<<<dim3(4, 2, 3), blk>>>(Wq, Wk, Wv, Wh, Wl);
    maskf_prep<<<kB, blk>>>(mask, maskf);

    // 1. Projections (fp16 MMA): grid (2 nx, 128 my, 3 w), 2 CTAs/SM.
    dim3 gproj(2, kM / 128, 3);
    proj_gemm<<<gproj, blk, PJ_SMEM>>>(Nb, Wh, Wl, bq, bk, bv, Qb, Kb, V);

    // 2. Scores: persistent warp-specialized, 148 CTAs x 320 threads.
    score_gemm<<<SC_GRID, SC_THREADS, SC_SMEM>>>(Qb, Kb, maskf, E, rpart,
                                                 0.0625f);

    // 3. colsum (inline invr), w-reduce + output contraction over fp16 V.
    colsum_stream_kernel<<<dim3(QCH, kB), blk>>>(E, rpart, wpart);
    out_part_kernel<<<dim3(N_KCHUNK, kB), blk>>>(wpart, V, opart);
    out_reduce_kernel<<<(kB * kD) / 256, blk>>>(opart, out);
}